// round 10
// baseline (speedup 1.0000x reference)
#include <cuda_runtime.h>
#include <math.h>

#define BB   128
#define NNOD 50
#define SEQ  51
#define DIM  128
#define NH   8
#define DHE  16
#define FFD  512
#define NLE  6
#define NLD  2
#define MTOT (BB*SEQ)            // 6528
#define SZ_MD (MTOT*DIM)         // 835584

// decoder smem cache layout
#define KCPAD 17
#define KCH   (NNOD*KCPAD)
#define KCSZ  (NLD*NH*KCH)
#define KFPAD 129
#define KFSZ  (SEQ*KFPAD)
#define DYN_FLOATS (2*KCSZ + KFSZ)
#define DYN_BYTES  (DYN_FLOATS*4)

// ---------------- scratch layout (slabs of SZ_MD floats) ----------------
#define OFF_H0   (0)
#define OFF_PT1  (1*SZ_MD)
#define OFF_PT2  (2*SZ_MD)
#define OFF_Q    (3*SZ_MD)         // 3 slabs (Q,K,V)
#define OFF_O    (6*SZ_MD)
#define OFF_F    (7*SZ_MD)         // 4 slabs
#define OFF_KATT (11*SZ_MD)        // 2 slabs
#define OFF_VATT (13*SZ_MD)        // 2 slabs
#define OFF_KFIN (15*SZ_MD)
#define OFF_PART (16*SZ_MD)        // 102*128*2 = 26112
#define OFF_BNA  (OFF_PART + 26624)  // 256
#define OFF_BNB  (OFF_BNA + 256)     // 256
#define OFF_PE   (OFF_BNB + 256)
#define SCRATCH_TOTAL (OFF_PE + NNOD*DIM)

__device__ float g_scratch[SCRATCH_TOTAL];

// ---------------- embedding ----------------
__global__ void embed_kernel(const float* __restrict__ x,
                             const float* __restrict__ w_in,
                             const float* __restrict__ b_in,
                             const float* __restrict__ start_ph,
                             float* __restrict__ h)
{
    int i = blockIdx.x * blockDim.x + threadIdx.x;
    if (i >= MTOT * DIM) return;
    int d = i & 127;
    int row = i >> 7;
    int s = row % SEQ;
    int b = row / SEQ;
    float v;
    if (s < NNOD) {
        const float* xp = x + (b * NNOD + s) * 2;
        v = xp[0] * w_in[d] + xp[1] * w_in[DIM + d] + b_in[d];
    } else {
        v = start_ph[d];
    }
    h[i] = v;
}

// ---------------- positional encoding ----------------
__global__ void pe_kernel(float* __restrict__ pe)
{
    int i = blockIdx.x * blockDim.x + threadIdx.x;
    if (i >= NNOD * DIM) return;
    int t = i >> 7, d = i & 127;
    double e = (double)(2 * (d / 2)) / 128.0;
    double ang = (double)t * pow(10000.0, -e);
    pe[i] = (float)(((d & 1) == 0) ? sin(ang) : cos(ang));
}

// ---------------- SGEMM (double-buffered, BN-fused) ----------------
// BNA: A' = A*bnA[k] + bnA[128+k]   (k = feature of A)
// BNR: v += R*bnR[n] + bnR[128+n]   (n = output col)   [RES must also be true]
// BNOUT: emit per-column (sum, sumsq) partials to part[(by*128 + n)*2 + {0,1}]
template<bool BIAS, bool RELU, bool RES, bool ZSTRIDE, bool BNA, bool BNR, bool BNOUT>
__global__ void __launch_bounds__(256) sgemm(const float* __restrict__ A,
                                             const float* __restrict__ W,
                                             const float* __restrict__ bias,
                                             const float* __restrict__ R,
                                             float* __restrict__ C,
                                             const float* __restrict__ bnA,
                                             const float* __restrict__ bnR,
                                             float* __restrict__ part,
                                             int M, int N, int K)
{
    if (ZSTRIDE) {
        int z = blockIdx.z;
        W += (size_t)z * K * N;
        if (BIAS) bias += (size_t)z * N;
        C += (size_t)z * M * N;
    }
    __shared__ float As[2][16][68];
    __shared__ float Bs[2][16][68];
    int bm = blockIdx.y * 64, bn = blockIdx.x * 64;
    int tid = threadIdx.x;
    int tr = tid >> 4, tc = tid & 15;
    int mA = tid >> 2, kkA = (tid & 3) * 4;
    int krB = tid >> 4, ccB = (tid & 15) * 4;
    float acc[4][4] = {};

    {
        float4 av = *(const float4*)&A[(bm + mA) * K + kkA];
        if (BNA) {
            av.x = av.x * bnA[kkA + 0] + bnA[128 + kkA + 0];
            av.y = av.y * bnA[kkA + 1] + bnA[128 + kkA + 1];
            av.z = av.z * bnA[kkA + 2] + bnA[128 + kkA + 2];
            av.w = av.w * bnA[kkA + 3] + bnA[128 + kkA + 3];
        }
        float4 bv = *(const float4*)&W[krB * N + bn + ccB];
        As[0][kkA + 0][mA] = av.x; As[0][kkA + 1][mA] = av.y;
        As[0][kkA + 2][mA] = av.z; As[0][kkA + 3][mA] = av.w;
        Bs[0][krB][ccB + 0] = bv.x; Bs[0][krB][ccB + 1] = bv.y;
        Bs[0][krB][ccB + 2] = bv.z; Bs[0][krB][ccB + 3] = bv.w;
    }
    __syncthreads();

    int buf = 0;
    for (int k0 = 0; k0 < K; k0 += 16) {
        bool more = (k0 + 16) < K;
        float4 av2, bv2;
        if (more) {
            int kb = k0 + 16 + kkA;
            av2 = *(const float4*)&A[(bm + mA) * K + kb];
            if (BNA) {
                av2.x = av2.x * bnA[kb + 0] + bnA[128 + kb + 0];
                av2.y = av2.y * bnA[kb + 1] + bnA[128 + kb + 1];
                av2.z = av2.z * bnA[kb + 2] + bnA[128 + kb + 2];
                av2.w = av2.w * bnA[kb + 3] + bnA[128 + kb + 3];
            }
            bv2 = *(const float4*)&W[(k0 + 16 + krB) * N + bn + ccB];
        }
#pragma unroll
        for (int k2 = 0; k2 < 16; k2++) {
            float ra[4], rb[4];
#pragma unroll
            for (int i = 0; i < 4; i++) { ra[i] = As[buf][k2][tr * 4 + i]; rb[i] = Bs[buf][k2][tc * 4 + i]; }
#pragma unroll
            for (int i = 0; i < 4; i++)
#pragma unroll
                for (int j = 0; j < 4; j++) acc[i][j] += ra[i] * rb[j];
        }
        if (more) {
            As[buf ^ 1][kkA + 0][mA] = av2.x; As[buf ^ 1][kkA + 1][mA] = av2.y;
            As[buf ^ 1][kkA + 2][mA] = av2.z; As[buf ^ 1][kkA + 3][mA] = av2.w;
            Bs[buf ^ 1][krB][ccB + 0] = bv2.x; Bs[buf ^ 1][krB][ccB + 1] = bv2.y;
            Bs[buf ^ 1][krB][ccB + 2] = bv2.z; Bs[buf ^ 1][krB][ccB + 3] = bv2.w;
        }
        __syncthreads();
        buf ^= 1;
    }

    float vout[4][4];
#pragma unroll
    for (int i = 0; i < 4; i++) {
        int m = bm + tr * 4 + i;
#pragma unroll
        for (int j = 0; j < 4; j++) {
            int n = bn + tc * 4 + j;
            float v = acc[i][j];
            if (BIAS) v += bias[n];
            if (RELU) v = fmaxf(v, 0.f);
            if (RES) {
                float r = R[m * N + n];
                if (BNR) v += r * bnR[n] + bnR[128 + n];
                else v += r;
            }
            C[m * N + n] = v;
            if (BNOUT) vout[i][j] = v;
        }
    }

    if (BNOUT) {
        // deterministic per-tile column partials
        float* rb = &As[0][0][0];   // 2176 floats available
#pragma unroll
        for (int j = 0; j < 4; j++) {
            int col = tc * 4 + j;
            float s = vout[0][j] + vout[1][j] + vout[2][j] + vout[3][j];
            float s2 = vout[0][j] * vout[0][j] + vout[1][j] * vout[1][j]
                     + vout[2][j] * vout[2][j] + vout[3][j] * vout[3][j];
            rb[(col * 16 + tr) * 2 + 0] = s;
            rb[(col * 16 + tr) * 2 + 1] = s2;
        }
        __syncthreads();
        if (tid < 64) {
            float s = 0.f, s2 = 0.f;
#pragma unroll
            for (int r = 0; r < 16; r++) {
                s  += rb[(tid * 16 + r) * 2 + 0];
                s2 += rb[(tid * 16 + r) * 2 + 1];
            }
            int gcol = bn + tid;
            part[(blockIdx.y * 128 + gcol) * 2 + 0] = s;
            part[(blockIdx.y * 128 + gcol) * 2 + 1] = s2;
        }
    }
}

// ---------------- BN reduce: partials -> scale/shift ----------------
__global__ void bn_reduce2(const float* __restrict__ part,
                           const float* __restrict__ gamma,
                           const float* __restrict__ beta,
                           float* __restrict__ bnout)
{
    int d = threadIdx.x;
    float s = 0.f, s2 = 0.f;
    for (int by = 0; by < 102; by++) {
        s  += part[(by * 128 + d) * 2 + 0];
        s2 += part[(by * 128 + d) * 2 + 1];
    }
    float m = s * (1.f / (float)MTOT);
    float var = s2 * (1.f / (float)MTOT) - m * m;
    float rstd = rsqrtf(var + 1e-5f);
    float scale = gamma[d] * rstd;
    bnout[d] = scale;
    bnout[128 + d] = beta[d] - m * scale;
}

// ---------------- encoder attention ----------------
__global__ void __launch_bounds__(256) enc_attn(const float* __restrict__ Q,
                                                const float* __restrict__ K,
                                                const float* __restrict__ V,
                                                float* __restrict__ O)
{
    __shared__ float Qs[SEQ][DHE], Ks[SEQ][DHE], Vs[SEQ][DHE];
    __shared__ float P[SEQ][SEQ + 1];
    int bh = blockIdx.x;
    int b = bh / NH, hh = bh % NH;
    int tid = threadIdx.x;
    for (int i = tid; i < SEQ * 4; i += 256) {
        int s = i >> 2, j4 = (i & 3) * 4;
        int g = (b * SEQ + s) * DIM + hh * DHE + j4;
        *(float4*)&Qs[s][j4] = *(const float4*)&Q[g];
        *(float4*)&Ks[s][j4] = *(const float4*)&K[g];
        *(float4*)&Vs[s][j4] = *(const float4*)&V[g];
    }
    __syncthreads();
    for (int p = tid; p < SEQ * SEQ; p += 256) {
        int q = p / SEQ, k = p % SEQ;
        float s = 0.f;
#pragma unroll
        for (int j = 0; j < DHE; j++) s += Qs[q][j] * Ks[k][j];
        P[q][k] = s * 0.25f;
    }
    __syncthreads();
    {
        int w = tid >> 5, lane = tid & 31;
        for (int q = w; q < SEQ; q += 8) {
            float v0 = (lane < SEQ) ? P[q][lane] : -1e30f;
            float v1 = (lane + 32 < SEQ) ? P[q][lane + 32] : -1e30f;
            float mx = fmaxf(v0, v1);
#pragma unroll
            for (int o = 16; o; o >>= 1) mx = fmaxf(mx, __shfl_xor_sync(0xffffffffu, mx, o));
            float e0 = (lane < SEQ) ? expf(v0 - mx) : 0.f;
            float e1 = (lane + 32 < SEQ) ? expf(v1 - mx) : 0.f;
            float sm = e0 + e1;
#pragma unroll
            for (int o = 16; o; o >>= 1) sm += __shfl_xor_sync(0xffffffffu, sm, o);
            float inv = 1.f / sm;
            if (lane < SEQ) P[q][lane] = e0 * inv;
            if (lane + 32 < SEQ) P[q][lane + 32] = e1 * inv;
        }
    }
    __syncthreads();
    for (int p = tid; p < SEQ * DHE; p += 256) {
        int q = p >> 4, j = p & 15;
        float s = 0.f;
        for (int k = 0; k < SEQ; k++) s += P[q][k] * Vs[k][j];
        O[(b * SEQ + q) * DIM + hh * DHE + j] = s;
    }
}

// ---------------- decoder helpers ----------------
__device__ __forceinline__ void gemv4_part(const float* __restrict__ x,
                                           const float* __restrict__ W,
                                           int c, int q16, float* acc)
{
    const float4* Wp = (const float4*)(W + (q16 * 8) * DIM) + c;
    const float* xp = x + q16 * 8;
#pragma unroll
    for (int k = 0; k < 8; k++) {
        float xk = xp[k];
        float4 w = Wp[k * 32];
        acc[0] += xk * w.x; acc[1] += xk * w.y;
        acc[2] += xk * w.z; acc[3] += xk * w.w;
    }
}

__device__ __forceinline__ void layernorm_fused(const float* __restrict__ su,
                                                float* __restrict__ ht,
                                                const float* __restrict__ gb,
                                                int tid, float* red2)
{
    int d = tid & 127;
    float x = su[d];
    float s = x, s2 = x * x;
#pragma unroll
    for (int o = 16; o; o >>= 1) {
        s  += __shfl_down_sync(0xffffffffu, s, o);
        s2 += __shfl_down_sync(0xffffffffu, s2, o);
    }
    int w = tid >> 5;
    if ((tid & 31) == 0) { red2[w] = s; red2[16 + w] = s2; }
    __syncthreads();
    float S = 0.f, S2 = 0.f;
#pragma unroll
    for (int i = 0; i < 16; i++) { S += red2[i]; S2 += red2[16 + i]; }
    float mean = S * (1.f / 512.f);
    float var = S2 * (1.f / 512.f) - mean * mean;
    float rstd = rsqrtf(var + 1e-5f);
    if (tid < 128) ht[d] = gb[d] * (x - mean) * rstd + gb[DIM + d];
    __syncthreads();
}

// ---------------- persistent decoder (R9 structure; BN applied on h_enc read) ----------------
__global__ void __launch_bounds__(512) decoder_kernel(
    const float* __restrict__ h_enc_raw, const float* __restrict__ bnB,
    const float* __restrict__ pe,
    const float* __restrict__ Katt, const float* __restrict__ Vatt,
    const float* __restrict__ Kfin,
    const float* __restrict__ dsw, const float* __restrict__ dsb,
    const float* __restrict__ dcw, const float* __restrict__ dcb,
    const float* __restrict__ dw1, const float* __restrict__ db1,
    const float* __restrict__ dw2, const float* __restrict__ db2,
    const float* __restrict__ dln, const float* __restrict__ wqf,
    float* __restrict__ out)
{
    extern __shared__ float dsm[];
    float* sKc   = dsm;
    float* sVc   = dsm + KCSZ;
    float* sKfin = dsm + 2 * KCSZ;

    int tid = threadIdx.x;
    int b = blockIdx.x;
    int d = tid & 127;
    int q4 = tid >> 7;
    int c = tid & 31;
    int q16 = tid >> 5;
    int hh = d >> 4, dh = d & 15;
    int wid = tid >> 5, lane = tid & 31;

    __shared__ float ht[DIM], sq[DIM], so[DIM], su[DIM];
    __shared__ float sf[FFD];
    __shared__ float pb0[2048], pb1[2048], pb2[2048];
    __shared__ float sc[NH][SEQ + 1];
    __shared__ float red2[32];
    __shared__ float slg[SEQ];
    __shared__ float sbn[2][DIM];
    __shared__ int   smask[SEQ];
    __shared__ int   scur;
    __shared__ float sslp;

    for (int i = tid; i < SEQ * DIM; i += 512) {
        int r = i >> 7, cc = i & 127;
        sKfin[r * KFPAD + cc] = Kfin[(b * SEQ + r) * DIM + cc];
    }
    if (tid < 256) sbn[tid >> 7][tid & 127] = bnB[tid];
    if (tid < SEQ) smask[tid] = (tid == NNOD) ? 1 : 0;
    if (tid == 0) { scur = NNOD; sslp = 0.f; }
    __syncthreads();

    for (int t = 0; t < NNOD; t++) {
        if (q4 == 0)
            ht[d] = h_enc_raw[(b * SEQ + scur) * DIM + d] * sbn[0][d] + sbn[1][d] + pe[t * DIM + d];
        __syncthreads();

        for (int l = 0; l < NLD; l++) {
            const float* W  = dsw + l * 4 * DIM * DIM;
            const float* bb = dsb + l * 4 * DIM;

            // ---- QKV ----
            {
                float aq[4] = {}, ak[4] = {}, av[4] = {};
                gemv4_part(ht, W,                 c, q16, aq);
                gemv4_part(ht, W + DIM * DIM,     c, q16, ak);
                gemv4_part(ht, W + 2 * DIM * DIM, c, q16, av);
                *(float4*)&pb0[q16 * 128 + c * 4] = make_float4(aq[0], aq[1], aq[2], aq[3]);
                *(float4*)&pb1[q16 * 128 + c * 4] = make_float4(ak[0], ak[1], ak[2], ak[3]);
                *(float4*)&pb2[q16 * 128 + c * 4] = make_float4(av[0], av[1], av[2], av[3]);
            }
            __syncthreads();
            {
                if (tid < 128) {
                    float s = bb[tid];
#pragma unroll
                    for (int qq = 0; qq < 16; qq++) s += pb0[qq * 128 + tid];
                    sq[tid] = s;
                } else if (tid < 256) {
                    int dd = tid - 128;
                    float s = bb[DIM + dd];
#pragma unroll
                    for (int qq = 0; qq < 16; qq++) s += pb1[qq * 128 + dd];
                    sKc[(l * NH + (dd >> 4)) * KCH + t * KCPAD + (dd & 15)] = s;
                } else if (tid < 384) {
                    int dd = tid - 256;
                    float s = bb[2 * DIM + dd];
#pragma unroll
                    for (int qq = 0; qq < 16; qq++) s += pb2[qq * 128 + dd];
                    sVc[(l * NH + (dd >> 4)) * KCH + t * KCPAD + (dd & 15)] = s;
                }
            }
            __syncthreads();

            int nt = t + 1;
            if (tid < NH * nt) {
                int ph = tid / nt, ps = tid % nt;
                const float* kp = &sKc[(l * NH + ph) * KCH + ps * KCPAD];
                const float* qp = &sq[ph * DHE];
                float s = 0.f;
#pragma unroll
                for (int j = 0; j < DHE; j++) s += qp[j] * kp[j];
                sc[ph][ps] = s * 0.25f;
            }
            __syncthreads();
            if (wid < NH) {
                float v0 = (lane < nt) ? sc[wid][lane] : -1e30f;
                float v1 = (lane + 32 < nt) ? sc[wid][lane + 32] : -1e30f;
                float mx = fmaxf(v0, v1);
#pragma unroll
                for (int o = 16; o; o >>= 1) mx = fmaxf(mx, __shfl_xor_sync(0xffffffffu, mx, o));
                float e0 = (lane < nt) ? expf(v0 - mx) : 0.f;
                float e1 = (lane + 32 < nt) ? expf(v1 - mx) : 0.f;
                float sm = e0 + e1;
#pragma unroll
                for (int o = 16; o; o >>= 1) sm += __shfl_xor_sync(0xffffffffu, sm, o);
                float inv = 1.f / sm;
                if (lane < nt) sc[wid][lane] = e0 * inv;
                if (lane + 32 < nt) sc[wid][lane + 32] = e1 * inv;
            }
            __syncthreads();
            {
                int s0 = (nt * q4) >> 2, s1 = (nt * (q4 + 1)) >> 2;
                const float* vp = &sVc[(l * NH + hh) * KCH + dh];
                float oo = 0.f;
#pragma unroll 4
                for (int s = s0; s < s1; s++) oo += sc[hh][s] * vp[s * KCPAD];
                pb0[q4 * 128 + d] = oo;
            }
            __syncthreads();
            if (tid < 128) so[tid] = pb0[tid] + pb0[128 + tid] + pb0[256 + tid] + pb0[384 + tid];
            __syncthreads();
            {
                float a[4] = {};
                gemv4_part(so, W + 3 * DIM * DIM, c, q16, a);
                *(float4*)&pb0[q16 * 128 + c * 4] = make_float4(a[0], a[1], a[2], a[3]);
            }
            __syncthreads();
            if (tid < 128) {
                float s = ht[tid] + bb[3 * DIM + tid];
#pragma unroll
                for (int qq = 0; qq < 16; qq++) s += pb0[qq * 128 + tid];
                su[tid] = s;
            }
            __syncthreads();
            layernorm_fused(su, ht, dln + ((l * 3 + 0) * 2) * DIM, tid, red2);

            // ---- cross attention ----
            const float* Wc = dcw + l * 2 * DIM * DIM;
            const float* bc = dcb + l * 2 * DIM;
            {
                float a[4] = {};
                gemv4_part(ht, Wc, c, q16, a);
                *(float4*)&pb0[q16 * 128 + c * 4] = make_float4(a[0], a[1], a[2], a[3]);
            }
            __syncthreads();
            if (tid < 128) {
                float s = bc[tid];
#pragma unroll
                for (int qq = 0; qq < 16; qq++) s += pb0[qq * 128 + tid];
                sq[tid] = s;
            }
            __syncthreads();
            if (tid < NH * SEQ) {
                int ph = tid / SEQ, pn = tid % SEQ;
                const float* kp = &Katt[(b * SEQ + pn) * (NLD * DIM) + l * DIM + ph * DHE];
                const float* qp = &sq[ph * DHE];
                float s = 0.f;
#pragma unroll
                for (int j = 0; j < DHE; j++) s += qp[j] * kp[j];
                sc[ph][pn] = s * 0.25f;
            }
            __syncthreads();
            if (wid < NH) {
                float v0 = (lane < SEQ) ? sc[wid][lane] : -1e30f;
                float v1 = (lane + 32 < SEQ) ? sc[wid][lane + 32] : -1e30f;
                float mx = fmaxf(v0, v1);
#pragma unroll
                for (int o = 16; o; o >>= 1) mx = fmaxf(mx, __shfl_xor_sync(0xffffffffu, mx, o));
                float e0 = (lane < SEQ) ? expf(v0 - mx) : 0.f;
                float e1 = (lane + 32 < SEQ) ? expf(v1 - mx) : 0.f;
                float sm = e0 + e1;
#pragma unroll
                for (int o = 16; o; o >>= 1) sm += __shfl_xor_sync(0xffffffffu, sm, o);
                float inv = 1.f / sm;
                if (lane < SEQ) sc[wid][lane] = e0 * inv;
                if (lane + 32 < SEQ) sc[wid][lane + 32] = e1 * inv;
            }
            __syncthreads();
            {
                int s0 = (SEQ * q4) >> 2, s1 = (SEQ * (q4 + 1)) >> 2;
                const float* vp = &Vatt[b * SEQ * (NLD * DIM) + l * DIM + d];
                float oo = 0.f;
#pragma unroll 4
                for (int n = s0; n < s1; n++) oo += sc[hh][n] * vp[n * NLD * DIM];
                pb0[q4 * 128 + d] = oo;
            }
            __syncthreads();
            if (tid < 128) so[tid] = pb0[tid] + pb0[128 + tid] + pb0[256 + tid] + pb0[384 + tid];
            __syncthreads();
            {
                float a[4] = {};
                gemv4_part(so, Wc + DIM * DIM, c, q16, a);
                *(float4*)&pb0[q16 * 128 + c * 4] = make_float4(a[0], a[1], a[2], a[3]);
            }
            __syncthreads();
            if (tid < 128) {
                float s = ht[tid] + bc[DIM + tid];
#pragma unroll
                for (int qq = 0; qq < 16; qq++) s += pb0[qq * 128 + tid];
                su[tid] = s;
            }
            __syncthreads();
            layernorm_fused(su, ht, dln + ((l * 3 + 1) * 2) * DIM, tid, red2);

            // ---- FFN1 ----
            {
                int cc = tid & 127;
                const float* W1 = dw1 + l * DIM * FFD;
                const float4* Wp = (const float4*)(W1 + (q4 * 32) * FFD) + cc;
                const float* xp = ht + q4 * 32;
                float a[4] = {};
#pragma unroll
                for (int k = 0; k < 32; k++) {
                    float xk = xp[k];
                    float4 w = Wp[k * 128];
                    a[0] += xk * w.x; a[1] += xk * w.y;
                    a[2] += xk * w.z; a[3] += xk * w.w;
                }
                *(float4*)&pb0[q4 * 512 + cc * 4] = make_float4(a[0], a[1], a[2], a[3]);
            }
            __syncthreads();
            sf[tid] = fmaxf(db1[l * FFD + tid] + pb0[tid] + pb0[512 + tid]
                            + pb0[1024 + tid] + pb0[1536 + tid], 0.f);
            __syncthreads();
            // ---- FFN2 ----
            {
                const float* W2 = dw2 + l * FFD * DIM;
                const float4* Wp = (const float4*)(W2 + (q16 * 32) * DIM) + c;
                const float* xp = sf + q16 * 32;
                float a[4] = {};
#pragma unroll
                for (int k = 0; k < 32; k++) {
                    float xk = xp[k];
                    float4 w = Wp[k * 32];
                    a[0] += xk * w.x; a[1] += xk * w.y;
                    a[2] += xk * w.z; a[3] += xk * w.w;
                }
                *(float4*)&pb0[q16 * 128 + c * 4] = make_float4(a[0], a[1], a[2], a[3]);
            }
            __syncthreads();
            if (tid < 128) {
                float s = ht[tid] + db2[l * DIM + tid];
#pragma unroll
                for (int qq = 0; qq < 16; qq++) s += pb0[qq * 128 + tid];
                su[tid] = s;
            }
            __syncthreads();
            layernorm_fused(su, ht, dln + ((l * 3 + 2) * 2) * DIM, tid, red2);
        }

        // ---- final pointer logits ----
        {
            float a[4] = {};
            gemv4_part(ht, wqf, c, q16, a);
            *(float4*)&pb0[q16 * 128 + c * 4] = make_float4(a[0], a[1], a[2], a[3]);
        }
        __syncthreads();
        if (tid < 128) {
            float s = 0.f;
#pragma unroll
            for (int qq = 0; qq < 16; qq++) s += pb0[qq * 128 + tid];
            sq[tid] = s;
        }
        __syncthreads();
        if (tid < SEQ) {
            const float* kp = &sKfin[tid * KFPAD];
            float a0 = 0.f, a1 = 0.f, a2 = 0.f, a3 = 0.f;
#pragma unroll
            for (int k = 0; k < 128; k += 4) {
                a0 += sq[k] * kp[k];
                a1 += sq[k + 1] * kp[k + 1];
                a2 += sq[k + 2] * kp[k + 2];
                a3 += sq[k + 3] * kp[k + 3];
            }
            float s = (a0 + a1) + (a2 + a3);
            float lg = 10.f * tanhf(s * 0.08838834764831845f);
            slg[tid] = smask[tid] ? -1e9f : lg;
        }
        __syncthreads();
        if (tid < 32) {
            float v0 = (tid < SEQ) ? slg[tid] : -2e30f; int i0 = tid;
            float v1 = (tid + 32 < SEQ) ? slg[tid + 32] : -2e30f;
            if (v1 > v0) { v0 = v1; i0 = tid + 32; }
#pragma unroll
            for (int o = 16; o; o >>= 1) {
                float vo = __shfl_xor_sync(0xffffffffu, v0, o);
                int io = __shfl_xor_sync(0xffffffffu, i0, o);
                if (vo > v0 || (vo == v0 && io < i0)) { v0 = vo; i0 = io; }
            }
            float e0 = (tid < SEQ) ? expf(slg[tid] - v0) : 0.f;
            float e1 = (tid + 32 < SEQ) ? expf(slg[tid + 32] - v0) : 0.f;
            float sm = e0 + e1;
#pragma unroll
            for (int o = 16; o; o >>= 1) sm += __shfl_xor_sync(0xffffffffu, sm, o);
            if (tid == 0) {
                sslp += -logf(sm);
                smask[i0] = 1;
                scur = i0;
                out[b * NNOD + t] = (float)i0;
            }
        }
        __syncthreads();
    }
    if (tid == 0) out[BB * NNOD + b] = sslp;
}

// ---------------- host launcher ----------------
extern "C" void kernel_launch(void* const* d_in, const int* in_sizes, int n_in,
                              void* d_out, int out_size)
{
    const float* x          = (const float*)d_in[0];
    const float* w_input    = (const float*)d_in[1];
    const float* b_input    = (const float*)d_in[2];
    const float* start_ph   = (const float*)d_in[3];
    const float* enc_attn_w = (const float*)d_in[4];
    const float* enc_attn_b = (const float*)d_in[5];
    const float* enc_ffn_w1 = (const float*)d_in[6];
    const float* enc_ffn_b1 = (const float*)d_in[7];
    const float* enc_ffn_w2 = (const float*)d_in[8];
    const float* enc_ffn_b2 = (const float*)d_in[9];
    const float* enc_bn     = (const float*)d_in[10];
    const float* dec_self_w = (const float*)d_in[11];
    const float* dec_self_b = (const float*)d_in[12];
    const float* dec_cross_w= (const float*)d_in[13];
    const float* dec_cross_b= (const float*)d_in[14];
    const float* dec_ffn_w1 = (const float*)d_in[15];
    const float* dec_ffn_b1 = (const float*)d_in[16];
    const float* dec_ffn_w2 = (const float*)d_in[17];
    const float* dec_ffn_b2 = (const float*)d_in[18];
    const float* dec_ln     = (const float*)d_in[19];
    const float* wk_dec     = (const float*)d_in[20];
    const float* bk_dec     = (const float*)d_in[21];
    const float* wv_dec     = (const float*)d_in[22];
    const float* bv_dec     = (const float*)d_in[23];
    const float* wq_final   = (const float*)d_in[24];
    const float* wk_final   = (const float*)d_in[25];
    float* out = (float*)d_out;

    float* base = nullptr;
    cudaGetSymbolAddress((void**)&base, g_scratch);
    float* ph    = base + OFF_H0;
    float* pt1   = base + OFF_PT1;
    float* pt2   = base + OFF_PT2;
    float* pQ    = base + OFF_Q;
    float* pO    = base + OFF_O;
    float* pf    = base + OFF_F;
    float* pKatt = base + OFF_KATT;
    float* pVatt = base + OFF_VATT;
    float* pKfin = base + OFF_KFIN;
    float* ppart = base + OFF_PART;
    float* pbnA  = base + OFF_BNA;
    float* pbnB  = base + OFF_BNB;
    float* ppe   = base + OFF_PE;

    cudaFuncSetAttribute(decoder_kernel, cudaFuncAttributeMaxDynamicSharedMemorySize, DYN_BYTES);

    embed_kernel<<<(MTOT * DIM + 255) / 256, 256>>>(x, w_input, b_input, start_ph, ph);
    pe_kernel<<<(NNOD * DIM + 255) / 256, 256>>>(ppe);

    dim3 gDD(DIM / 64, MTOT / 64);
    dim3 gQKV(DIM / 64, MTOT / 64, 3);
    dim3 gDF(FFD / 64, MTOT / 64);
    dim3 gD2(256 / 64, MTOT / 64);

    for (int l = 0; l < NLE; l++) {
        const float* aw = enc_attn_w + (size_t)l * 4 * DIM * DIM;
        const float* ab = enc_attn_b + (size_t)l * 4 * DIM;
        const float* Araw = (l == 0) ? ph : pt2;

        // QKV (BN of previous layer folded into A for l>0)
        if (l == 0)
            sgemm<true, false, false, true, false, false, false><<<gQKV, 256>>>(
                Araw, aw, ab, nullptr, pQ, nullptr, nullptr, nullptr, MTOT, DIM, DIM);
        else
            sgemm<true, false, false, true, true, false, false><<<gQKV, 256>>>(
                Araw, aw, ab, nullptr, pQ, pbnB, nullptr, nullptr, MTOT, DIM, DIM);

        enc_attn<<<BB * NH, 256>>>(pQ, pQ + SZ_MD, pQ + 2 * SZ_MD, pO);

        // Wo + residual(raw h, BN folded for l>0) + BN stats out
        if (l == 0)
            sgemm<true, false, true, false, false, false, true><<<gDD, 256>>>(
                pO, aw + 3 * DIM * DIM, ab + 3 * DIM, Araw, pt1, nullptr, nullptr, ppart, MTOT, DIM, DIM);
        else
            sgemm<true, false, true, false, false, true, true><<<gDD, 256>>>(
                pO, aw + 3 * DIM * DIM, ab + 3 * DIM, Araw, pt1, nullptr, pbnB, ppart, MTOT, DIM, DIM);

        bn_reduce2<<<1, 128>>>(ppart, enc_bn + ((l * 2 + 0) * 2 + 0) * DIM,
                               enc_bn + ((l * 2 + 0) * 2 + 1) * DIM, pbnA);

        // FFN1: A = pt1 with BN(A) folded
        sgemm<true, true, false, false, true, false, false><<<gDF, 256>>>(
            pt1, enc_ffn_w1 + (size_t)l * DIM * FFD, enc_ffn_b1 + (size_t)l * FFD,
            nullptr, pf, pbnA, nullptr, nullptr, MTOT, FFD, DIM);

        // FFN2: residual = pt1 with BN folded, BN stats out
        sgemm<true, false, true, false, false, true, true><<<gDD, 256>>>(
            pf, enc_ffn_w2 + (size_t)l * FFD * DIM, enc_ffn_b2 + (size_t)l * DIM,
            pt1, pt2, nullptr, pbnA, ppart, MTOT, DIM, FFD);

        bn_reduce2<<<1, 128>>>(ppart, enc_bn + ((l * 2 + 1) * 2 + 0) * DIM,
                               enc_bn + ((l * 2 + 1) * 2 + 1) * DIM, pbnB);
    }

    // decoder cross K/V and final keys: A = pt2 with final BN folded
    sgemm<true, false, false, false, true, false, false><<<gD2, 256>>>(
        pt2, wk_dec, bk_dec, nullptr, pKatt, pbnB, nullptr, nullptr, MTOT, NLD * DIM, DIM);
    sgemm<true, false, false, false, true, false, false><<<gD2, 256>>>(
        pt2, wv_dec, bv_dec, nullptr, pVatt, pbnB, nullptr, nullptr, MTOT, NLD * DIM, DIM);
    sgemm<false, false, false, false, true, false, false><<<gDD, 256>>>(
        pt2, wk_final, nullptr, nullptr, pKfin, pbnB, nullptr, nullptr, MTOT, DIM, DIM);

    decoder_kernel<<<BB, 512, DYN_BYTES>>>(pt2, pbnB, ppe, pKatt, pVatt, pKfin,
                                dec_self_w, dec_self_b, dec_cross_w, dec_cross_b,
                                dec_ffn_w1, dec_ffn_b1, dec_ffn_w2, dec_ffn_b2,
                                dec_ln, wq_final, out);
}

// round 12
// speedup vs baseline: 1.2658x; 1.2658x over previous
#include <cuda_runtime.h>
#include <math.h>

#define BB   128
#define NNOD 50
#define SEQ  51
#define DIM  128
#define NH   8
#define DHE  16
#define FFD  512
#define NLE  6
#define NLD  2
#define MTOT (BB*SEQ)            // 6528
#define SZ_MD (MTOT*DIM)         // 835584

// decoder smem cache layout
#define KCPAD 17
#define KCH   (NNOD*KCPAD)
#define KCSZ  (NLD*NH*KCH)       // 13600
#define KFPAD 129
#define KFSZ  (SEQ*KFPAD)        // 6579
#define KFSZ_AL 6580             // padded to keep next slab 16B-aligned
#define VATSZ (SEQ*NLD*DIM)      // 13056
#define DYN_FLOATS (2*KCSZ + KFSZ_AL + VATSZ)
#define DYN_BYTES  (DYN_FLOATS*4)

// ---------------- scratch ----------------
#define OFF_H0   (0)
#define OFF_PT1  (1*SZ_MD)
#define OFF_PT2  (2*SZ_MD)
#define OFF_Q    (3*SZ_MD)
#define OFF_O    (6*SZ_MD)
#define OFF_F    (7*SZ_MD)
#define OFF_KATT (11*SZ_MD)
#define OFF_VATT (13*SZ_MD)
#define OFF_KFIN (15*SZ_MD)
#define OFF_PART (16*SZ_MD)          // 64*256 = 16384
#define OFF_BNA  (OFF_PART + 16384)
#define OFF_BNB  (OFF_BNA + 256)
#define OFF_PE   (OFF_BNB + 256)
#define SCRATCH_TOTAL (OFF_PE + NNOD*DIM)

__device__ float g_scratch[SCRATCH_TOTAL];

// ---------------- embedding ----------------
__global__ void embed_kernel(const float* __restrict__ x,
                             const float* __restrict__ w_in,
                             const float* __restrict__ b_in,
                             const float* __restrict__ start_ph,
                             float* __restrict__ h)
{
    int i = blockIdx.x * blockDim.x + threadIdx.x;
    if (i >= MTOT * DIM) return;
    int d = i & 127;
    int row = i >> 7;
    int s = row % SEQ;
    int b = row / SEQ;
    float v;
    if (s < NNOD) {
        const float* xp = x + (b * NNOD + s) * 2;
        v = xp[0] * w_in[d] + xp[1] * w_in[DIM + d] + b_in[d];
    } else {
        v = start_ph[d];
    }
    h[i] = v;
}

// ---------------- positional encoding ----------------
__global__ void pe_kernel(float* __restrict__ pe)
{
    int i = blockIdx.x * blockDim.x + threadIdx.x;
    if (i >= NNOD * DIM) return;
    int t = i >> 7, d = i & 127;
    double e = (double)(2 * (d / 2)) / 128.0;
    double ang = (double)t * pow(10000.0, -e);
    pe[i] = (float)(((d & 1) == 0) ? sin(ang) : cos(ang));
}

// ---------------- SGEMM (double-buffered; optional BN-folded A / residual) ----------------
// BNA: A' = A*bnA[k] + bnA[128+k]; BNR: v += R*bnR[n] + bnR[128+n] (RES must be true)
template<bool BIAS, bool RELU, bool RES, bool ZSTRIDE, bool BNA, bool BNR>
__global__ void __launch_bounds__(256) sgemm(const float* __restrict__ A,
                                             const float* __restrict__ W,
                                             const float* __restrict__ bias,
                                             const float* __restrict__ R,
                                             float* __restrict__ C,
                                             const float* __restrict__ bnA,
                                             const float* __restrict__ bnR,
                                             int M, int N, int K)
{
    if (ZSTRIDE) {
        int z = blockIdx.z;
        W += (size_t)z * K * N;
        if (BIAS) bias += (size_t)z * N;
        C += (size_t)z * M * N;
    }
    __shared__ float As[2][16][68];
    __shared__ float Bs[2][16][68];
    int bm = blockIdx.y * 64, bn = blockIdx.x * 64;
    int tid = threadIdx.x;
    int tr = tid >> 4, tc = tid & 15;
    int mA = tid >> 2, kkA = (tid & 3) * 4;
    int krB = tid >> 4, ccB = (tid & 15) * 4;
    float acc[4][4] = {};

    {
        float4 av = *(const float4*)&A[(bm + mA) * K + kkA];
        if (BNA) {
            av.x = av.x * bnA[kkA + 0] + bnA[128 + kkA + 0];
            av.y = av.y * bnA[kkA + 1] + bnA[128 + kkA + 1];
            av.z = av.z * bnA[kkA + 2] + bnA[128 + kkA + 2];
            av.w = av.w * bnA[kkA + 3] + bnA[128 + kkA + 3];
        }
        float4 bv = *(const float4*)&W[krB * N + bn + ccB];
        As[0][kkA + 0][mA] = av.x; As[0][kkA + 1][mA] = av.y;
        As[0][kkA + 2][mA] = av.z; As[0][kkA + 3][mA] = av.w;
        Bs[0][krB][ccB + 0] = bv.x; Bs[0][krB][ccB + 1] = bv.y;
        Bs[0][krB][ccB + 2] = bv.z; Bs[0][krB][ccB + 3] = bv.w;
    }
    __syncthreads();

    int buf = 0;
    for (int k0 = 0; k0 < K; k0 += 16) {
        bool more = (k0 + 16) < K;
        float4 av2, bv2;
        if (more) {
            int kb = k0 + 16 + kkA;
            av2 = *(const float4*)&A[(bm + mA) * K + kb];
            if (BNA) {
                av2.x = av2.x * bnA[kb + 0] + bnA[128 + kb + 0];
                av2.y = av2.y * bnA[kb + 1] + bnA[128 + kb + 1];
                av2.z = av2.z * bnA[kb + 2] + bnA[128 + kb + 2];
                av2.w = av2.w * bnA[kb + 3] + bnA[128 + kb + 3];
            }
            bv2 = *(const float4*)&W[(k0 + 16 + krB) * N + bn + ccB];
        }
#pragma unroll
        for (int k2 = 0; k2 < 16; k2++) {
            float ra[4], rb[4];
#pragma unroll
            for (int i = 0; i < 4; i++) { ra[i] = As[buf][k2][tr * 4 + i]; rb[i] = Bs[buf][k2][tc * 4 + i]; }
#pragma unroll
            for (int i = 0; i < 4; i++)
#pragma unroll
                for (int j = 0; j < 4; j++) acc[i][j] += ra[i] * rb[j];
        }
        if (more) {
            As[buf ^ 1][kkA + 0][mA] = av2.x; As[buf ^ 1][kkA + 1][mA] = av2.y;
            As[buf ^ 1][kkA + 2][mA] = av2.z; As[buf ^ 1][kkA + 3][mA] = av2.w;
            Bs[buf ^ 1][krB][ccB + 0] = bv2.x; Bs[buf ^ 1][krB][ccB + 1] = bv2.y;
            Bs[buf ^ 1][krB][ccB + 2] = bv2.z; Bs[buf ^ 1][krB][ccB + 3] = bv2.w;
        }
        __syncthreads();
        buf ^= 1;
    }
#pragma unroll
    for (int i = 0; i < 4; i++) {
        int m = bm + tr * 4 + i;
#pragma unroll
        for (int j = 0; j < 4; j++) {
            int n = bn + tc * 4 + j;
            float v = acc[i][j];
            if (BIAS) v += bias[n];
            if (RELU) v = fmaxf(v, 0.f);
            if (RES) {
                float r = R[m * N + n];
                if (BNR) v += r * bnR[n] + bnR[128 + n];
                else v += r;
            }
            C[m * N + n] = v;
        }
    }
}

// ---------------- BatchNorm stats + scale/shift reduce ----------------
__global__ void __launch_bounds__(256) bn_partial(const float* __restrict__ X,
                                                  float* __restrict__ part)
{
    int d = threadIdx.x & 127, half = threadIdx.x >> 7;
    int r0 = blockIdx.x * 102;
    float s = 0.f, ss = 0.f;
    for (int r = r0 + half; r < r0 + 102; r += 2) {
        float v = X[r * DIM + d];
        s += v; ss += v * v;
    }
    __shared__ float sh[2][2][128];
    sh[half][0][d] = s; sh[half][1][d] = ss;
    __syncthreads();
    if (!half) {
        part[blockIdx.x * 256 + d]       = s + sh[1][0][d];
        part[blockIdx.x * 256 + 128 + d] = ss + sh[1][1][d];
    }
}

__global__ void bn_reduce3(const float* __restrict__ part,
                           const float* __restrict__ gamma,
                           const float* __restrict__ beta,
                           float* __restrict__ bnout)
{
    int d = threadIdx.x;
    float s = 0.f, ss = 0.f;
    for (int b = 0; b < 64; b++) { s += part[b * 256 + d]; ss += part[b * 256 + 128 + d]; }
    float m = s * (1.f / (float)MTOT);
    float v = ss * (1.f / (float)MTOT) - m * m;
    float rstd = rsqrtf(v + 1e-5f);
    float scale = gamma[d] * rstd;
    bnout[d] = scale;
    bnout[128 + d] = beta[d] - m * scale;
}

// ---------------- encoder attention ----------------
__global__ void __launch_bounds__(256) enc_attn(const float* __restrict__ Q,
                                                const float* __restrict__ K,
                                                const float* __restrict__ V,
                                                float* __restrict__ O)
{
    __shared__ float Qs[SEQ][DHE], Ks[SEQ][DHE], Vs[SEQ][DHE];
    __shared__ float P[SEQ][SEQ + 1];
    int bh = blockIdx.x;
    int b = bh / NH, hh = bh % NH;
    int tid = threadIdx.x;
    for (int i = tid; i < SEQ * 4; i += 256) {
        int s = i >> 2, j4 = (i & 3) * 4;
        int g = (b * SEQ + s) * DIM + hh * DHE + j4;
        *(float4*)&Qs[s][j4] = *(const float4*)&Q[g];
        *(float4*)&Ks[s][j4] = *(const float4*)&K[g];
        *(float4*)&Vs[s][j4] = *(const float4*)&V[g];
    }
    __syncthreads();
    for (int p = tid; p < SEQ * SEQ; p += 256) {
        int q = p / SEQ, k = p % SEQ;
        float s = 0.f;
#pragma unroll
        for (int j = 0; j < DHE; j++) s += Qs[q][j] * Ks[k][j];
        P[q][k] = s * 0.25f;
    }
    __syncthreads();
    {
        int w = tid >> 5, lane = tid & 31;
        for (int q = w; q < SEQ; q += 8) {
            float v0 = (lane < SEQ) ? P[q][lane] : -1e30f;
            float v1 = (lane + 32 < SEQ) ? P[q][lane + 32] : -1e30f;
            float mx = fmaxf(v0, v1);
#pragma unroll
            for (int o = 16; o; o >>= 1) mx = fmaxf(mx, __shfl_xor_sync(0xffffffffu, mx, o));
            float e0 = (lane < SEQ) ? expf(v0 - mx) : 0.f;
            float e1 = (lane + 32 < SEQ) ? expf(v1 - mx) : 0.f;
            float sm = e0 + e1;
#pragma unroll
            for (int o = 16; o; o >>= 1) sm += __shfl_xor_sync(0xffffffffu, sm, o);
            float inv = 1.f / sm;
            if (lane < SEQ) P[q][lane] = e0 * inv;
            if (lane + 32 < SEQ) P[q][lane + 32] = e1 * inv;
        }
    }
    __syncthreads();
    for (int p = tid; p < SEQ * DHE; p += 256) {
        int q = p >> 4, j = p & 15;
        float s = 0.f;
        for (int k = 0; k < SEQ; k++) s += P[q][k] * Vs[k][j];
        O[(b * SEQ + q) * DIM + hh * DHE + j] = s;
    }
}

// ---------------- decoder helpers ----------------
__device__ __forceinline__ void gemv4_part(const float* __restrict__ x,
                                           const float* __restrict__ W,
                                           int c, int q16, float* acc)
{
    const float4* Wp = (const float4*)(W + (q16 * 8) * DIM) + c;
    const float* xp = x + q16 * 8;
#pragma unroll
    for (int k = 0; k < 8; k++) {
        float xk = xp[k];
        float4 w = Wp[k * 32];
        acc[0] += xk * w.x; acc[1] += xk * w.y;
        acc[2] += xk * w.z; acc[3] += xk * w.w;
    }
}

__device__ __forceinline__ void layernorm_fused(const float* __restrict__ su,
                                                float* __restrict__ ht,
                                                const float* __restrict__ gb,
                                                int tid, float* red2)
{
    int d = tid & 127;
    float x = su[d];
    float s = x, s2 = x * x;
#pragma unroll
    for (int o = 16; o; o >>= 1) {
        s  += __shfl_down_sync(0xffffffffu, s, o);
        s2 += __shfl_down_sync(0xffffffffu, s2, o);
    }
    int w = tid >> 5;
    if ((tid & 31) == 0) { red2[w] = s; red2[16 + w] = s2; }
    __syncthreads();
    float S = 0.f, S2 = 0.f;
#pragma unroll
    for (int i = 0; i < 16; i++) { S += red2[i]; S2 += red2[16 + i]; }
    float mean = S * (1.f / 512.f);
    float var = S2 * (1.f / 512.f) - mean * mean;
    float rstd = rsqrtf(var + 1e-5f);
    if (tid < 128) ht[d] = gb[d] * (x - mean) * rstd + gb[DIM + d];
    __syncthreads();
}

// ---------------- persistent decoder (Vatt in smem + BN on h_enc read) ----------------
__global__ void __launch_bounds__(512) decoder_kernel(
    const float* __restrict__ h_enc_raw, const float* __restrict__ bnB,
    const float* __restrict__ pe,
    const float* __restrict__ Katt, const float* __restrict__ Vatt,
    const float* __restrict__ Kfin,
    const float* __restrict__ dsw, const float* __restrict__ dsb,
    const float* __restrict__ dcw, const float* __restrict__ dcb,
    const float* __restrict__ dw1, const float* __restrict__ db1,
    const float* __restrict__ dw2, const float* __restrict__ db2,
    const float* __restrict__ dln, const float* __restrict__ wqf,
    float* __restrict__ out)
{
    extern __shared__ float dsm[];
    float* sKc   = dsm;
    float* sVc   = dsm + KCSZ;
    float* sKfin = dsm + 2 * KCSZ;
    float* sVatt = dsm + 2 * KCSZ + KFSZ_AL;   // 16B-aligned slab

    int tid = threadIdx.x;
    int b = blockIdx.x;
    int d = tid & 127;
    int q4 = tid >> 7;
    int c = tid & 31;
    int q16 = tid >> 5;
    int hh = d >> 4, dh = d & 15;
    int wid = tid >> 5, lane = tid & 31;

    __shared__ float ht[DIM], sq[DIM], so[DIM], su[DIM];
    __shared__ float sf[FFD];
    __shared__ float pb0[2048], pb1[2048], pb2[2048];
    __shared__ float sc[NH][SEQ + 1];
    __shared__ float red2[32];
    __shared__ float slg[SEQ];
    __shared__ float sbn[2][DIM];
    __shared__ int   smask[SEQ];
    __shared__ int   scur;
    __shared__ float sslp;

    for (int i = tid; i < SEQ * DIM; i += 512) {
        int r = i >> 7, cc = i & 127;
        sKfin[r * KFPAD + cc] = Kfin[(b * SEQ + r) * DIM + cc];
    }
    {
        const float4* src = (const float4*)(Vatt + (size_t)b * VATSZ);
        float4* dst = (float4*)sVatt;
        for (int i = tid; i < VATSZ / 4; i += 512) dst[i] = src[i];
    }
    if (tid < 256) sbn[tid >> 7][tid & 127] = bnB[tid];
    if (tid < SEQ) smask[tid] = (tid == NNOD) ? 1 : 0;
    if (tid == 0) { scur = NNOD; sslp = 0.f; }
    __syncthreads();

    for (int t = 0; t < NNOD; t++) {
        if (q4 == 0)
            ht[d] = h_enc_raw[(b * SEQ + scur) * DIM + d] * sbn[0][d] + sbn[1][d] + pe[t * DIM + d];
        __syncthreads();

        for (int l = 0; l < NLD; l++) {
            const float* W  = dsw + l * 4 * DIM * DIM;
            const float* bb = dsb + l * 4 * DIM;

            // ---- QKV ----
            {
                float aq[4] = {}, ak[4] = {}, av[4] = {};
                gemv4_part(ht, W,                 c, q16, aq);
                gemv4_part(ht, W + DIM * DIM,     c, q16, ak);
                gemv4_part(ht, W + 2 * DIM * DIM, c, q16, av);
                *(float4*)&pb0[q16 * 128 + c * 4] = make_float4(aq[0], aq[1], aq[2], aq[3]);
                *(float4*)&pb1[q16 * 128 + c * 4] = make_float4(ak[0], ak[1], ak[2], ak[3]);
                *(float4*)&pb2[q16 * 128 + c * 4] = make_float4(av[0], av[1], av[2], av[3]);
            }
            __syncthreads();
            {
                if (tid < 128) {
                    float s = bb[tid];
#pragma unroll
                    for (int qq = 0; qq < 16; qq++) s += pb0[qq * 128 + tid];
                    sq[tid] = s;
                } else if (tid < 256) {
                    int dd = tid - 128;
                    float s = bb[DIM + dd];
#pragma unroll
                    for (int qq = 0; qq < 16; qq++) s += pb1[qq * 128 + dd];
                    sKc[(l * NH + (dd >> 4)) * KCH + t * KCPAD + (dd & 15)] = s;
                } else if (tid < 384) {
                    int dd = tid - 256;
                    float s = bb[2 * DIM + dd];
#pragma unroll
                    for (int qq = 0; qq < 16; qq++) s += pb2[qq * 128 + dd];
                    sVc[(l * NH + (dd >> 4)) * KCH + t * KCPAD + (dd & 15)] = s;
                }
            }
            __syncthreads();

            int nt = t + 1;
            if (tid < NH * nt) {
                int ph = tid / nt, ps = tid % nt;
                const float* kp = &sKc[(l * NH + ph) * KCH + ps * KCPAD];
                const float* qp = &sq[ph * DHE];
                float s = 0.f;
#pragma unroll
                for (int j = 0; j < DHE; j++) s += qp[j] * kp[j];
                sc[ph][ps] = s * 0.25f;
            }
            __syncthreads();
            if (wid < NH) {
                float v0 = (lane < nt) ? sc[wid][lane] : -1e30f;
                float v1 = (lane + 32 < nt) ? sc[wid][lane + 32] : -1e30f;
                float mx = fmaxf(v0, v1);
#pragma unroll
                for (int o = 16; o; o >>= 1) mx = fmaxf(mx, __shfl_xor_sync(0xffffffffu, mx, o));
                float e0 = (lane < nt) ? expf(v0 - mx) : 0.f;
                float e1 = (lane + 32 < nt) ? expf(v1 - mx) : 0.f;
                float sm = e0 + e1;
#pragma unroll
                for (int o = 16; o; o >>= 1) sm += __shfl_xor_sync(0xffffffffu, sm, o);
                float inv = 1.f / sm;
                if (lane < nt) sc[wid][lane] = e0 * inv;
                if (lane + 32 < nt) sc[wid][lane + 32] = e1 * inv;
            }
            __syncthreads();
            {
                int s0 = (nt * q4) >> 2, s1 = (nt * (q4 + 1)) >> 2;
                const float* vp = &sVc[(l * NH + hh) * KCH + dh];
                float oo = 0.f;
#pragma unroll 4
                for (int s = s0; s < s1; s++) oo += sc[hh][s] * vp[s * KCPAD];
                pb0[q4 * 128 + d] = oo;
            }
            __syncthreads();
            if (tid < 128) so[tid] = pb0[tid] + pb0[128 + tid] + pb0[256 + tid] + pb0[384 + tid];
            __syncthreads();
            {
                float a[4] = {};
                gemv4_part(so, W + 3 * DIM * DIM, c, q16, a);
                *(float4*)&pb0[q16 * 128 + c * 4] = make_float4(a[0], a[1], a[2], a[3]);
            }
            __syncthreads();
            if (tid < 128) {
                float s = ht[tid] + bb[3 * DIM + tid];
#pragma unroll
                for (int qq = 0; qq < 16; qq++) s += pb0[qq * 128 + tid];
                su[tid] = s;
            }
            __syncthreads();
            layernorm_fused(su, ht, dln + ((l * 3 + 0) * 2) * DIM, tid, red2);

            // ---- cross attention ----
            const float* Wc = dcw + l * 2 * DIM * DIM;
            const float* bc = dcb + l * 2 * DIM;
            {
                float a[4] = {};
                gemv4_part(ht, Wc, c, q16, a);
                *(float4*)&pb0[q16 * 128 + c * 4] = make_float4(a[0], a[1], a[2], a[3]);
            }
            __syncthreads();
            if (tid < 128) {
                float s = bc[tid];
#pragma unroll
                for (int qq = 0; qq < 16; qq++) s += pb0[qq * 128 + tid];
                sq[tid] = s;
            }
            __syncthreads();
            if (tid < NH * SEQ) {
                int ph = tid / SEQ, pn = tid % SEQ;
                const float* kp = &Katt[(b * SEQ + pn) * (NLD * DIM) + l * DIM + ph * DHE];
                const float* qp = &sq[ph * DHE];
                float s = 0.f;
#pragma unroll
                for (int j = 0; j < DHE; j++) s += qp[j] * kp[j];
                sc[ph][pn] = s * 0.25f;
            }
            __syncthreads();
            if (wid < NH) {
                float v0 = (lane < SEQ) ? sc[wid][lane] : -1e30f;
                float v1 = (lane + 32 < SEQ) ? sc[wid][lane + 32] : -1e30f;
                float mx = fmaxf(v0, v1);
#pragma unroll
                for (int o = 16; o; o >>= 1) mx = fmaxf(mx, __shfl_xor_sync(0xffffffffu, mx, o));
                float e0 = (lane < SEQ) ? expf(v0 - mx) : 0.f;
                float e1 = (lane + 32 < SEQ) ? expf(v1 - mx) : 0.f;
                float sm = e0 + e1;
#pragma unroll
                for (int o = 16; o; o >>= 1) sm += __shfl_xor_sync(0xffffffffu, sm, o);
                float inv = 1.f / sm;
                if (lane < SEQ) sc[wid][lane] = e0 * inv;
                if (lane + 32 < SEQ) sc[wid][lane + 32] = e1 * inv;
            }
            __syncthreads();
            {
                int s0 = (SEQ * q4) >> 2, s1 = (SEQ * (q4 + 1)) >> 2;
                const float* vp = &sVatt[l * DIM + d];
                float oo = 0.f;
#pragma unroll 4
                for (int n = s0; n < s1; n++) oo += sc[hh][n] * vp[n * (NLD * DIM)];
                pb0[q4 * 128 + d] = oo;
            }
            __syncthreads();
            if (tid < 128) so[tid] = pb0[tid] + pb0[128 + tid] + pb0[256 + tid] + pb0[384 + tid];
            __syncthreads();
            {
                float a[4] = {};
                gemv4_part(so, Wc + DIM * DIM, c, q16, a);
                *(float4*)&pb0[q16 * 128 + c * 4] = make_float4(a[0], a[1], a[2], a[3]);
            }
            __syncthreads();
            if (tid < 128) {
                float s = ht[tid] + bc[DIM + tid];
#pragma unroll
                for (int qq = 0; qq < 16; qq++) s += pb0[qq * 128 + tid];
                su[tid] = s;
            }
            __syncthreads();
            layernorm_fused(su, ht, dln + ((l * 3 + 1) * 2) * DIM, tid, red2);

            // ---- FFN1 ----
            {
                int cc = tid & 127;
                const float* W1 = dw1 + l * DIM * FFD;
                const float4* Wp = (const float4*)(W1 + (q4 * 32) * FFD) + cc;
                const float* xp = ht + q4 * 32;
                float a[4] = {};
#pragma unroll
                for (int k = 0; k < 32; k++) {
                    float xk = xp[k];
                    float4 w = Wp[k * 128];
                    a[0] += xk * w.x; a[1] += xk * w.y;
                    a[2] += xk * w.z; a[3] += xk * w.w;
                }
                *(float4*)&pb0[q4 * 512 + cc * 4] = make_float4(a[0], a[1], a[2], a[3]);
            }
            __syncthreads();
            sf[tid] = fmaxf(db1[l * FFD + tid] + pb0[tid] + pb0[512 + tid]
                            + pb0[1024 + tid] + pb0[1536 + tid], 0.f);
            __syncthreads();
            // ---- FFN2 ----
            {
                const float* W2 = dw2 + l * FFD * DIM;
                const float4* Wp = (const float4*)(W2 + (q16 * 32) * DIM) + c;
                const float* xp = sf + q16 * 32;
                float a[4] = {};
#pragma unroll
                for (int k = 0; k < 32; k++) {
                    float xk = xp[k];
                    float4 w = Wp[k * 32];
                    a[0] += xk * w.x; a[1] += xk * w.y;
                    a[2] += xk * w.z; a[3] += xk * w.w;
                }
                *(float4*)&pb0[q16 * 128 + c * 4] = make_float4(a[0], a[1], a[2], a[3]);
            }
            __syncthreads();
            if (tid < 128) {
                float s = ht[tid] + db2[l * DIM + tid];
#pragma unroll
                for (int qq = 0; qq < 16; qq++) s += pb0[qq * 128 + tid];
                su[tid] = s;
            }
            __syncthreads();
            layernorm_fused(su, ht, dln + ((l * 3 + 2) * 2) * DIM, tid, red2);
        }

        // ---- final pointer logits ----
        {
            float a[4] = {};
            gemv4_part(ht, wqf, c, q16, a);
            *(float4*)&pb0[q16 * 128 + c * 4] = make_float4(a[0], a[1], a[2], a[3]);
        }
        __syncthreads();
        if (tid < 128) {
            float s = 0.f;
#pragma unroll
            for (int qq = 0; qq < 16; qq++) s += pb0[qq * 128 + tid];
            sq[tid] = s;
        }
        __syncthreads();
        if (tid < SEQ) {
            const float* kp = &sKfin[tid * KFPAD];
            float a0 = 0.f, a1 = 0.f, a2 = 0.f, a3 = 0.f;
#pragma unroll
            for (int k = 0; k < 128; k += 4) {
                a0 += sq[k] * kp[k];
                a1 += sq[k + 1] * kp[k + 1];
                a2 += sq[k + 2] * kp[k + 2];
                a3 += sq[k + 3] * kp[k + 3];
            }
            float s = (a0 + a1) + (a2 + a3);
            float lg = 10.f * tanhf(s * 0.08838834764831845f);
            slg[tid] = smask[tid] ? -1e9f : lg;
        }
        __syncthreads();
        if (tid < 32) {
            float v0 = (tid < SEQ) ? slg[tid] : -2e30f; int i0 = tid;
            float v1 = (tid + 32 < SEQ) ? slg[tid + 32] : -2e30f;
            if (v1 > v0) { v0 = v1; i0 = tid + 32; }
#pragma unroll
            for (int o = 16; o; o >>= 1) {
                float vo = __shfl_xor_sync(0xffffffffu, v0, o);
                int io = __shfl_xor_sync(0xffffffffu, i0, o);
                if (vo > v0 || (vo == v0 && io < i0)) { v0 = vo; i0 = io; }
            }
            float e0 = (tid < SEQ) ? expf(slg[tid] - v0) : 0.f;
            float e1 = (tid + 32 < SEQ) ? expf(slg[tid + 32] - v0) : 0.f;
            float sm = e0 + e1;
#pragma unroll
            for (int o = 16; o; o >>= 1) sm += __shfl_xor_sync(0xffffffffu, sm, o);
            if (tid == 0) {
                sslp += -logf(sm);
                smask[i0] = 1;
                scur = i0;
                out[b * NNOD + t] = (float)i0;
            }
        }
        __syncthreads();
    }
    if (tid == 0) out[BB * NNOD + b] = sslp;
}

// ---------------- host launcher ----------------
extern "C" void kernel_launch(void* const* d_in, const int* in_sizes, int n_in,
                              void* d_out, int out_size)
{
    const float* x          = (const float*)d_in[0];
    const float* w_input    = (const float*)d_in[1];
    const float* b_input    = (const float*)d_in[2];
    const float* start_ph   = (const float*)d_in[3];
    const float* enc_attn_w = (const float*)d_in[4];
    const float* enc_attn_b = (const float*)d_in[5];
    const float* enc_ffn_w1 = (const float*)d_in[6];
    const float* enc_ffn_b1 = (const float*)d_in[7];
    const float* enc_ffn_w2 = (const float*)d_in[8];
    const float* enc_ffn_b2 = (const float*)d_in[9];
    const float* enc_bn     = (const float*)d_in[10];
    const float* dec_self_w = (const float*)d_in[11];
    const float* dec_self_b = (const float*)d_in[12];
    const float* dec_cross_w= (const float*)d_in[13];
    const float* dec_cross_b= (const float*)d_in[14];
    const float* dec_ffn_w1 = (const float*)d_in[15];
    const float* dec_ffn_b1 = (const float*)d_in[16];
    const float* dec_ffn_w2 = (const float*)d_in[17];
    const float* dec_ffn_b2 = (const float*)d_in[18];
    const float* dec_ln     = (const float*)d_in[19];
    const float* wk_dec     = (const float*)d_in[20];
    const float* bk_dec     = (const float*)d_in[21];
    const float* wv_dec     = (const float*)d_in[22];
    const float* bv_dec     = (const float*)d_in[23];
    const float* wq_final   = (const float*)d_in[24];
    const float* wk_final   = (const float*)d_in[25];
    float* out = (float*)d_out;

    float* base = nullptr;
    cudaGetSymbolAddress((void**)&base, g_scratch);
    float* ph    = base + OFF_H0;
    float* pt1   = base + OFF_PT1;
    float* pt2   = base + OFF_PT2;
    float* pQ    = base + OFF_Q;
    float* pO    = base + OFF_O;
    float* pf    = base + OFF_F;
    float* pKatt = base + OFF_KATT;
    float* pVatt = base + OFF_VATT;
    float* pKfin = base + OFF_KFIN;
    float* ppart = base + OFF_PART;
    float* pbnA  = base + OFF_BNA;
    float* pbnB  = base + OFF_BNB;
    float* ppe   = base + OFF_PE;

    cudaFuncSetAttribute(decoder_kernel, cudaFuncAttributeMaxDynamicSharedMemorySize, DYN_BYTES);

    embed_kernel<<<(MTOT * DIM + 255) / 256, 256>>>(x, w_input, b_input, start_ph, ph);
    pe_kernel<<<(NNOD * DIM + 255) / 256, 256>>>(ppe);

    dim3 gDD(DIM / 64, MTOT / 64);
    dim3 gQKV(DIM / 64, MTOT / 64, 3);
    dim3 gDF(FFD / 64, MTOT / 64);
    dim3 gD2(256 / 64, MTOT / 64);

    for (int l = 0; l < NLE; l++) {
        const float* aw = enc_attn_w + (size_t)l * 4 * DIM * DIM;
        const float* ab = enc_attn_b + (size_t)l * 4 * DIM;
        const float* Araw = (l == 0) ? ph : pt2;

        if (l == 0)
            sgemm<true, false, false, true, false, false><<<gQKV, 256>>>(
                Araw, aw, ab, nullptr, pQ, nullptr, nullptr, MTOT, DIM, DIM);
        else
            sgemm<true, false, false, true, true, false><<<gQKV, 256>>>(
                Araw, aw, ab, nullptr, pQ, pbnB, nullptr, MTOT, DIM, DIM);

        enc_attn<<<BB * NH, 256>>>(pQ, pQ + SZ_MD, pQ + 2 * SZ_MD, pO);

        if (l == 0)
            sgemm<true, false, true, false, false, false><<<gDD, 256>>>(
                pO, aw + 3 * DIM * DIM, ab + 3 * DIM, Araw, pt1, nullptr, nullptr, MTOT, DIM, DIM);
        else
            sgemm<true, false, true, false, false, true><<<gDD, 256>>>(
                pO, aw + 3 * DIM * DIM, ab + 3 * DIM, Araw, pt1, nullptr, pbnB, MTOT, DIM, DIM);

        bn_partial<<<64, 256>>>(pt1, ppart);
        bn_reduce3<<<1, 128>>>(ppart, enc_bn + ((l * 2 + 0) * 2 + 0) * DIM,
                               enc_bn + ((l * 2 + 0) * 2 + 1) * DIM, pbnA);

        sgemm<true, true, false, false, true, false><<<gDF, 256>>>(
            pt1, enc_ffn_w1 + (size_t)l * DIM * FFD, enc_ffn_b1 + (size_t)l * FFD,
            nullptr, pf, pbnA, nullptr, MTOT, FFD, DIM);

        sgemm<true, false, true, false, false, true><<<gDD, 256>>>(
            pf, enc_ffn_w2 + (size_t)l * FFD * DIM, enc_ffn_b2 + (size_t)l * DIM,
            pt1, pt2, nullptr, pbnA, MTOT, DIM, FFD);

        bn_partial<<<64, 256>>>(pt2, ppart);
        bn_reduce3<<<1, 128>>>(ppart, enc_bn + ((l * 2 + 1) * 2 + 0) * DIM,
                               enc_bn + ((l * 2 + 1) * 2 + 1) * DIM, pbnB);
    }

    sgemm<true, false, false, false, true, false><<<gD2, 256>>>(
        pt2, wk_dec, bk_dec, nullptr, pKatt, pbnB, nullptr, MTOT, NLD * DIM, DIM);
    sgemm<true, false, false, false, true, false><<<gD2, 256>>>(
        pt2, wv_dec, bv_dec, nullptr, pVatt, pbnB, nullptr, MTOT, NLD * DIM, DIM);
    sgemm<false, false, false, false, true, false><<<gDD, 256>>>(
        pt2, wk_final, nullptr, nullptr, pKfin, pbnB, nullptr, MTOT, DIM, DIM);

    decoder_kernel<<<BB, 512, DYN_BYTES>>>(pt2, pbnB, ppe, pKatt, pVatt, pKfin,
                                dec_self_w, dec_self_b, dec_cross_w, dec_cross_b,
                                dec_ffn_w1, dec_ffn_b1, dec_ffn_w2, dec_ffn_b2,
                                dec_ln, wq_final, out);
}

// round 13
// speedup vs baseline: 1.3121x; 1.0366x over previous
#include <cuda_runtime.h>
#include <math.h>

#define BB   128
#define NNOD 50
#define SEQ  51
#define DIM  128
#define NH   8
#define DHE  16
#define FFD  512
#define NLE  6
#define NLD  2
#define MTOT (BB*SEQ)            // 6528
#define SZ_MD (MTOT*DIM)         // 835584

// decoder smem cache layout
#define KCPAD 17
#define KCH   (NNOD*KCPAD)
#define KCSZ  (NLD*NH*KCH)       // 13600
#define KFPAD 129
#define KFSZ  (SEQ*KFPAD)        // 6579
#define KFSZ_AL 6580             // padded to keep next slab 16B-aligned
#define VATSZ (SEQ*NLD*DIM)      // 13056
#define DYN_FLOATS (2*KCSZ + KFSZ_AL + VATSZ)
#define DYN_BYTES  (DYN_FLOATS*4)

// ---------------- scratch ----------------
#define OFF_H0   (0)
#define OFF_PT1  (1*SZ_MD)
#define OFF_PT2  (2*SZ_MD)
#define OFF_Q    (3*SZ_MD)
#define OFF_O    (6*SZ_MD)
#define OFF_F    (7*SZ_MD)
#define OFF_KATT (11*SZ_MD)
#define OFF_VATT (13*SZ_MD)
#define OFF_KFIN (15*SZ_MD)
#define OFF_PART (16*SZ_MD)          // 64*256 = 16384
#define OFF_BNA  (OFF_PART + 16384)
#define OFF_BNB  (OFF_BNA + 256)
#define OFF_PE   (OFF_BNB + 256)
#define SCRATCH_TOTAL (OFF_PE + NNOD*DIM)

__device__ float g_scratch[SCRATCH_TOTAL];
__device__ int   g_bn_counter = 0;

// ---------------- embedding ----------------
__global__ void embed_kernel(const float* __restrict__ x,
                             const float* __restrict__ w_in,
                             const float* __restrict__ b_in,
                             const float* __restrict__ start_ph,
                             float* __restrict__ h)
{
    int i = blockIdx.x * blockDim.x + threadIdx.x;
    if (i >= MTOT * DIM) return;
    int d = i & 127;
    int row = i >> 7;
    int s = row % SEQ;
    int b = row / SEQ;
    float v;
    if (s < NNOD) {
        const float* xp = x + (b * NNOD + s) * 2;
        v = xp[0] * w_in[d] + xp[1] * w_in[DIM + d] + b_in[d];
    } else {
        v = start_ph[d];
    }
    h[i] = v;
}

// ---------------- positional encoding ----------------
__global__ void pe_kernel(float* __restrict__ pe)
{
    int i = blockIdx.x * blockDim.x + threadIdx.x;
    if (i >= NNOD * DIM) return;
    int t = i >> 7, d = i & 127;
    double e = (double)(2 * (d / 2)) / 128.0;
    double ang = (double)t * pow(10000.0, -e);
    pe[i] = (float)(((d & 1) == 0) ? sin(ang) : cos(ang));
}

// ---------------- SGEMM (double-buffered; optional BN-folded A / residual) ----------------
template<bool BIAS, bool RELU, bool RES, bool ZSTRIDE, bool BNA, bool BNR>
__global__ void __launch_bounds__(256) sgemm(const float* __restrict__ A,
                                             const float* __restrict__ W,
                                             const float* __restrict__ bias,
                                             const float* __restrict__ R,
                                             float* __restrict__ C,
                                             const float* __restrict__ bnA,
                                             const float* __restrict__ bnR,
                                             int M, int N, int K)
{
    if (ZSTRIDE) {
        int z = blockIdx.z;
        W += (size_t)z * K * N;
        if (BIAS) bias += (size_t)z * N;
        C += (size_t)z * M * N;
    }
    __shared__ float As[2][16][68];
    __shared__ float Bs[2][16][68];
    int bm = blockIdx.y * 64, bn = blockIdx.x * 64;
    int tid = threadIdx.x;
    int tr = tid >> 4, tc = tid & 15;
    int mA = tid >> 2, kkA = (tid & 3) * 4;
    int krB = tid >> 4, ccB = (tid & 15) * 4;
    float acc[4][4] = {};

    {
        float4 av = *(const float4*)&A[(bm + mA) * K + kkA];
        if (BNA) {
            av.x = av.x * bnA[kkA + 0] + bnA[128 + kkA + 0];
            av.y = av.y * bnA[kkA + 1] + bnA[128 + kkA + 1];
            av.z = av.z * bnA[kkA + 2] + bnA[128 + kkA + 2];
            av.w = av.w * bnA[kkA + 3] + bnA[128 + kkA + 3];
        }
        float4 bv = *(const float4*)&W[krB * N + bn + ccB];
        As[0][kkA + 0][mA] = av.x; As[0][kkA + 1][mA] = av.y;
        As[0][kkA + 2][mA] = av.z; As[0][kkA + 3][mA] = av.w;
        Bs[0][krB][ccB + 0] = bv.x; Bs[0][krB][ccB + 1] = bv.y;
        Bs[0][krB][ccB + 2] = bv.z; Bs[0][krB][ccB + 3] = bv.w;
    }
    __syncthreads();

    int buf = 0;
    for (int k0 = 0; k0 < K; k0 += 16) {
        bool more = (k0 + 16) < K;
        float4 av2, bv2;
        if (more) {
            int kb = k0 + 16 + kkA;
            av2 = *(const float4*)&A[(bm + mA) * K + kb];
            if (BNA) {
                av2.x = av2.x * bnA[kb + 0] + bnA[128 + kb + 0];
                av2.y = av2.y * bnA[kb + 1] + bnA[128 + kb + 1];
                av2.z = av2.z * bnA[kb + 2] + bnA[128 + kb + 2];
                av2.w = av2.w * bnA[kb + 3] + bnA[128 + kb + 3];
            }
            bv2 = *(const float4*)&W[(k0 + 16 + krB) * N + bn + ccB];
        }
#pragma unroll
        for (int k2 = 0; k2 < 16; k2++) {
            float ra[4], rb[4];
#pragma unroll
            for (int i = 0; i < 4; i++) { ra[i] = As[buf][k2][tr * 4 + i]; rb[i] = Bs[buf][k2][tc * 4 + i]; }
#pragma unroll
            for (int i = 0; i < 4; i++)
#pragma unroll
                for (int j = 0; j < 4; j++) acc[i][j] += ra[i] * rb[j];
        }
        if (more) {
            As[buf ^ 1][kkA + 0][mA] = av2.x; As[buf ^ 1][kkA + 1][mA] = av2.y;
            As[buf ^ 1][kkA + 2][mA] = av2.z; As[buf ^ 1][kkA + 3][mA] = av2.w;
            Bs[buf ^ 1][krB][ccB + 0] = bv2.x; Bs[buf ^ 1][krB][ccB + 1] = bv2.y;
            Bs[buf ^ 1][krB][ccB + 2] = bv2.z; Bs[buf ^ 1][krB][ccB + 3] = bv2.w;
        }
        __syncthreads();
        buf ^= 1;
    }
#pragma unroll
    for (int i = 0; i < 4; i++) {
        int m = bm + tr * 4 + i;
#pragma unroll
        for (int j = 0; j < 4; j++) {
            int n = bn + tc * 4 + j;
            float v = acc[i][j];
            if (BIAS) v += bias[n];
            if (RELU) v = fmaxf(v, 0.f);
            if (RES) {
                float r = R[m * N + n];
                if (BNR) v += r * bnR[n] + bnR[128 + n];
                else v += r;
            }
            C[m * N + n] = v;
        }
    }
}

// ---------------- fused BN stats: partial + last-block reduce ----------------
__global__ void __launch_bounds__(256) bn_stats(const float* __restrict__ X,
                                                float* __restrict__ part,
                                                const float* __restrict__ gamma,
                                                const float* __restrict__ beta,
                                                float* __restrict__ bnout)
{
    int d = threadIdx.x & 127, half = threadIdx.x >> 7;
    int r0 = blockIdx.x * 102;
    float s = 0.f, ss = 0.f;
    for (int r = r0 + half; r < r0 + 102; r += 2) {
        float v = X[r * DIM + d];
        s += v; ss += v * v;
    }
    __shared__ float sh[2][2][128];
    __shared__ bool isLast;
    sh[half][0][d] = s; sh[half][1][d] = ss;
    __syncthreads();
    if (!half) {
        part[blockIdx.x * 256 + d]       = s + sh[1][0][d];
        part[blockIdx.x * 256 + 128 + d] = ss + sh[1][1][d];
    }
    __threadfence();
    __syncthreads();
    if (threadIdx.x == 0) isLast = (atomicAdd(&g_bn_counter, 1) == 63);
    __syncthreads();
    if (isLast) {
        __threadfence();
        if (threadIdx.x < 128) {
            float S = 0.f, SS = 0.f;
            for (int b = 0; b < 64; b++) {
                S  += part[b * 256 + d];
                SS += part[b * 256 + 128 + d];
            }
            float m = S * (1.f / (float)MTOT);
            float v = SS * (1.f / (float)MTOT) - m * m;
            float rstd = rsqrtf(v + 1e-5f);
            float scale = gamma[d] * rstd;
            bnout[d] = scale;
            bnout[128 + d] = beta[d] - m * scale;
        }
        if (threadIdx.x == 0) g_bn_counter = 0;
    }
}

// ---------------- encoder attention v3: register-cached Q, float4 LDS ----------------
__global__ void __launch_bounds__(256) enc_attn(const float* __restrict__ Q,
                                                const float* __restrict__ K,
                                                const float* __restrict__ V,
                                                float* __restrict__ O)
{
    __shared__ __align__(16) float Qs[SEQ][20], Ks[SEQ][20], Vs[SEQ][20];
    __shared__ float P[SEQ][SEQ + 1];
    int bh = blockIdx.x;
    int b = bh / NH, hh = bh % NH;
    int tid = threadIdx.x;
    for (int i = tid; i < SEQ * 4; i += 256) {
        int s = i >> 2, j4 = (i & 3) * 4;
        int g = (b * SEQ + s) * DIM + hh * DHE + j4;
        *(float4*)&Qs[s][j4] = *(const float4*)&Q[g];
        *(float4*)&Ks[s][j4] = *(const float4*)&K[g];
        *(float4*)&Vs[s][j4] = *(const float4*)&V[g];
    }
    __syncthreads();
    // QK^T: 5 threads per q-row; Q row cached in registers
    {
        int q = tid / 5, i5 = tid % 5;
        if (q < SEQ) {
            float4 q0 = *(const float4*)&Qs[q][0];
            float4 q1 = *(const float4*)&Qs[q][4];
            float4 q2 = *(const float4*)&Qs[q][8];
            float4 q3 = *(const float4*)&Qs[q][12];
            for (int k = i5; k < SEQ; k += 5) {
                float4 k0 = *(const float4*)&Ks[k][0];
                float4 k1 = *(const float4*)&Ks[k][4];
                float4 k2 = *(const float4*)&Ks[k][8];
                float4 k3 = *(const float4*)&Ks[k][12];
                float s = q0.x * k0.x + q0.y * k0.y + q0.z * k0.z + q0.w * k0.w
                        + q1.x * k1.x + q1.y * k1.y + q1.z * k1.z + q1.w * k1.w
                        + q2.x * k2.x + q2.y * k2.y + q2.z * k2.z + q2.w * k2.w
                        + q3.x * k3.x + q3.y * k3.y + q3.z * k3.z + q3.w * k3.w;
                P[q][k] = s * 0.25f;
            }
        }
    }
    __syncthreads();
    // warp-per-row softmax
    {
        int w = tid >> 5, lane = tid & 31;
        for (int q = w; q < SEQ; q += 8) {
            float v0 = (lane < SEQ) ? P[q][lane] : -1e30f;
            float v1 = (lane + 32 < SEQ) ? P[q][lane + 32] : -1e30f;
            float mx = fmaxf(v0, v1);
#pragma unroll
            for (int o = 16; o; o >>= 1) mx = fmaxf(mx, __shfl_xor_sync(0xffffffffu, mx, o));
            float e0 = (lane < SEQ) ? expf(v0 - mx) : 0.f;
            float e1 = (lane + 32 < SEQ) ? expf(v1 - mx) : 0.f;
            float sm = e0 + e1;
#pragma unroll
            for (int o = 16; o; o >>= 1) sm += __shfl_xor_sync(0xffffffffu, sm, o);
            float inv = 1.f / sm;
            if (lane < SEQ) P[q][lane] = e0 * inv;
            if (lane + 32 < SEQ) P[q][lane + 32] = e1 * inv;
        }
    }
    __syncthreads();
    // P @ V: one float4 of output per thread
    if (tid < SEQ * 4) {
        int q = tid >> 2, j4 = (tid & 3) * 4;
        float4 acc = make_float4(0.f, 0.f, 0.f, 0.f);
        for (int k = 0; k < SEQ; k++) {
            float pk = P[q][k];
            float4 v = *(const float4*)&Vs[k][j4];
            acc.x += pk * v.x; acc.y += pk * v.y;
            acc.z += pk * v.z; acc.w += pk * v.w;
        }
        *(float4*)&O[(b * SEQ + q) * DIM + hh * DHE + j4] = acc;
    }
}

// ---------------- decoder helpers ----------------
__device__ __forceinline__ void gemv4_part(const float* __restrict__ x,
                                           const float* __restrict__ W,
                                           int c, int q16, float* acc)
{
    const float4* Wp = (const float4*)(W + (q16 * 8) * DIM) + c;
    const float* xp = x + q16 * 8;
#pragma unroll
    for (int k = 0; k < 8; k++) {
        float xk = xp[k];
        float4 w = Wp[k * 32];
        acc[0] += xk * w.x; acc[1] += xk * w.y;
        acc[2] += xk * w.z; acc[3] += xk * w.w;
    }
}

__device__ __forceinline__ void layernorm_fused(const float* __restrict__ su,
                                                float* __restrict__ ht,
                                                const float* __restrict__ gb,
                                                int tid, float* red2)
{
    int d = tid & 127;
    float x = su[d];
    float s = x, s2 = x * x;
#pragma unroll
    for (int o = 16; o; o >>= 1) {
        s  += __shfl_down_sync(0xffffffffu, s, o);
        s2 += __shfl_down_sync(0xffffffffu, s2, o);
    }
    int w = tid >> 5;
    if ((tid & 31) == 0) { red2[w] = s; red2[16 + w] = s2; }
    __syncthreads();
    float S = 0.f, S2 = 0.f;
#pragma unroll
    for (int i = 0; i < 16; i++) { S += red2[i]; S2 += red2[16 + i]; }
    float mean = S * (1.f / 512.f);
    float var = S2 * (1.f / 512.f) - mean * mean;
    float rstd = rsqrtf(var + 1e-5f);
    if (tid < 128) ht[d] = gb[d] * (x - mean) * rstd + gb[DIM + d];
    __syncthreads();
}

// ---------------- persistent decoder (R12) ----------------
__global__ void __launch_bounds__(512) decoder_kernel(
    const float* __restrict__ h_enc_raw, const float* __restrict__ bnB,
    const float* __restrict__ pe,
    const float* __restrict__ Katt, const float* __restrict__ Vatt,
    const float* __restrict__ Kfin,
    const float* __restrict__ dsw, const float* __restrict__ dsb,
    const float* __restrict__ dcw, const float* __restrict__ dcb,
    const float* __restrict__ dw1, const float* __restrict__ db1,
    const float* __restrict__ dw2, const float* __restrict__ db2,
    const float* __restrict__ dln, const float* __restrict__ wqf,
    float* __restrict__ out)
{
    extern __shared__ float dsm[];
    float* sKc   = dsm;
    float* sVc   = dsm + KCSZ;
    float* sKfin = dsm + 2 * KCSZ;
    float* sVatt = dsm + 2 * KCSZ + KFSZ_AL;

    int tid = threadIdx.x;
    int b = blockIdx.x;
    int d = tid & 127;
    int q4 = tid >> 7;
    int c = tid & 31;
    int q16 = tid >> 5;
    int hh = d >> 4, dh = d & 15;
    int wid = tid >> 5, lane = tid & 31;

    __shared__ float ht[DIM], sq[DIM], so[DIM], su[DIM];
    __shared__ float sf[FFD];
    __shared__ float pb0[2048], pb1[2048], pb2[2048];
    __shared__ float sc[NH][SEQ + 1];
    __shared__ float red2[32];
    __shared__ float slg[SEQ];
    __shared__ float sbn[2][DIM];
    __shared__ int   smask[SEQ];
    __shared__ int   scur;
    __shared__ float sslp;

    for (int i = tid; i < SEQ * DIM; i += 512) {
        int r = i >> 7, cc = i & 127;
        sKfin[r * KFPAD + cc] = Kfin[(b * SEQ + r) * DIM + cc];
    }
    {
        const float4* src = (const float4*)(Vatt + (size_t)b * VATSZ);
        float4* dst = (float4*)sVatt;
        for (int i = tid; i < VATSZ / 4; i += 512) dst[i] = src[i];
    }
    if (tid < 256) sbn[tid >> 7][tid & 127] = bnB[tid];
    if (tid < SEQ) smask[tid] = (tid == NNOD) ? 1 : 0;
    if (tid == 0) { scur = NNOD; sslp = 0.f; }
    __syncthreads();

    for (int t = 0; t < NNOD; t++) {
        if (q4 == 0)
            ht[d] = h_enc_raw[(b * SEQ + scur) * DIM + d] * sbn[0][d] + sbn[1][d] + pe[t * DIM + d];
        __syncthreads();

        for (int l = 0; l < NLD; l++) {
            const float* W  = dsw + l * 4 * DIM * DIM;
            const float* bb = dsb + l * 4 * DIM;

            // ---- QKV ----
            {
                float aq[4] = {}, ak[4] = {}, av[4] = {};
                gemv4_part(ht, W,                 c, q16, aq);
                gemv4_part(ht, W + DIM * DIM,     c, q16, ak);
                gemv4_part(ht, W + 2 * DIM * DIM, c, q16, av);
                *(float4*)&pb0[q16 * 128 + c * 4] = make_float4(aq[0], aq[1], aq[2], aq[3]);
                *(float4*)&pb1[q16 * 128 + c * 4] = make_float4(ak[0], ak[1], ak[2], ak[3]);
                *(float4*)&pb2[q16 * 128 + c * 4] = make_float4(av[0], av[1], av[2], av[3]);
            }
            __syncthreads();
            {
                if (tid < 128) {
                    float s = bb[tid];
#pragma unroll
                    for (int qq = 0; qq < 16; qq++) s += pb0[qq * 128 + tid];
                    sq[tid] = s;
                } else if (tid < 256) {
                    int dd = tid - 128;
                    float s = bb[DIM + dd];
#pragma unroll
                    for (int qq = 0; qq < 16; qq++) s += pb1[qq * 128 + dd];
                    sKc[(l * NH + (dd >> 4)) * KCH + t * KCPAD + (dd & 15)] = s;
                } else if (tid < 384) {
                    int dd = tid - 256;
                    float s = bb[2 * DIM + dd];
#pragma unroll
                    for (int qq = 0; qq < 16; qq++) s += pb2[qq * 128 + dd];
                    sVc[(l * NH + (dd >> 4)) * KCH + t * KCPAD + (dd & 15)] = s;
                }
            }
            __syncthreads();

            int nt = t + 1;
            if (tid < NH * nt) {
                int ph = tid / nt, ps = tid % nt;
                const float* kp = &sKc[(l * NH + ph) * KCH + ps * KCPAD];
                const float* qp = &sq[ph * DHE];
                float s = 0.f;
#pragma unroll
                for (int j = 0; j < DHE; j++) s += qp[j] * kp[j];
                sc[ph][ps] = s * 0.25f;
            }
            __syncthreads();
            if (wid < NH) {
                float v0 = (lane < nt) ? sc[wid][lane] : -1e30f;
                float v1 = (lane + 32 < nt) ? sc[wid][lane + 32] : -1e30f;
                float mx = fmaxf(v0, v1);
#pragma unroll
                for (int o = 16; o; o >>= 1) mx = fmaxf(mx, __shfl_xor_sync(0xffffffffu, mx, o));
                float e0 = (lane < nt) ? expf(v0 - mx) : 0.f;
                float e1 = (lane + 32 < nt) ? expf(v1 - mx) : 0.f;
                float sm = e0 + e1;
#pragma unroll
                for (int o = 16; o; o >>= 1) sm += __shfl_xor_sync(0xffffffffu, sm, o);
                float inv = 1.f / sm;
                if (lane < nt) sc[wid][lane] = e0 * inv;
                if (lane + 32 < nt) sc[wid][lane + 32] = e1 * inv;
            }
            __syncthreads();
            {
                int s0 = (nt * q4) >> 2, s1 = (nt * (q4 + 1)) >> 2;
                const float* vp = &sVc[(l * NH + hh) * KCH + dh];
                float oo = 0.f;
#pragma unroll 4
                for (int s = s0; s < s1; s++) oo += sc[hh][s] * vp[s * KCPAD];
                pb0[q4 * 128 + d] = oo;
            }
            __syncthreads();
            if (tid < 128) so[tid] = pb0[tid] + pb0[128 + tid] + pb0[256 + tid] + pb0[384 + tid];
            __syncthreads();
            {
                float a[4] = {};
                gemv4_part(so, W + 3 * DIM * DIM, c, q16, a);
                *(float4*)&pb0[q16 * 128 + c * 4] = make_float4(a[0], a[1], a[2], a[3]);
            }
            __syncthreads();
            if (tid < 128) {
                float s = ht[tid] + bb[3 * DIM + tid];
#pragma unroll
                for (int qq = 0; qq < 16; qq++) s += pb0[qq * 128 + tid];
                su[tid] = s;
            }
            __syncthreads();
            layernorm_fused(su, ht, dln + ((l * 3 + 0) * 2) * DIM, tid, red2);

            // ---- cross attention ----
            const float* Wc = dcw + l * 2 * DIM * DIM;
            const float* bc = dcb + l * 2 * DIM;
            {
                float a[4] = {};
                gemv4_part(ht, Wc, c, q16, a);
                *(float4*)&pb0[q16 * 128 + c * 4] = make_float4(a[0], a[1], a[2], a[3]);
            }
            __syncthreads();
            if (tid < 128) {
                float s = bc[tid];
#pragma unroll
                for (int qq = 0; qq < 16; qq++) s += pb0[qq * 128 + tid];
                sq[tid] = s;
            }
            __syncthreads();
            if (tid < NH * SEQ) {
                int ph = tid / SEQ, pn = tid % SEQ;
                const float* kp = &Katt[(b * SEQ + pn) * (NLD * DIM) + l * DIM + ph * DHE];
                const float* qp = &sq[ph * DHE];
                float s = 0.f;
#pragma unroll
                for (int j = 0; j < DHE; j++) s += qp[j] * kp[j];
                sc[ph][pn] = s * 0.25f;
            }
            __syncthreads();
            if (wid < NH) {
                float v0 = (lane < SEQ) ? sc[wid][lane] : -1e30f;
                float v1 = (lane + 32 < SEQ) ? sc[wid][lane + 32] : -1e30f;
                float mx = fmaxf(v0, v1);
#pragma unroll
                for (int o = 16; o; o >>= 1) mx = fmaxf(mx, __shfl_xor_sync(0xffffffffu, mx, o));
                float e0 = (lane < SEQ) ? expf(v0 - mx) : 0.f;
                float e1 = (lane + 32 < SEQ) ? expf(v1 - mx) : 0.f;
                float sm = e0 + e1;
#pragma unroll
                for (int o = 16; o; o >>= 1) sm += __shfl_xor_sync(0xffffffffu, sm, o);
                float inv = 1.f / sm;
                if (lane < SEQ) sc[wid][lane] = e0 * inv;
                if (lane + 32 < SEQ) sc[wid][lane + 32] = e1 * inv;
            }
            __syncthreads();
            {
                int s0 = (SEQ * q4) >> 2, s1 = (SEQ * (q4 + 1)) >> 2;
                const float* vp = &sVatt[l * DIM + d];
                float oo = 0.f;
#pragma unroll 4
                for (int n = s0; n < s1; n++) oo += sc[hh][n] * vp[n * (NLD * DIM)];
                pb0[q4 * 128 + d] = oo;
            }
            __syncthreads();
            if (tid < 128) so[tid] = pb0[tid] + pb0[128 + tid] + pb0[256 + tid] + pb0[384 + tid];
            __syncthreads();
            {
                float a[4] = {};
                gemv4_part(so, Wc + DIM * DIM, c, q16, a);
                *(float4*)&pb0[q16 * 128 + c * 4] = make_float4(a[0], a[1], a[2], a[3]);
            }
            __syncthreads();
            if (tid < 128) {
                float s = ht[tid] + bc[DIM + tid];
#pragma unroll
                for (int qq = 0; qq < 16; qq++) s += pb0[qq * 128 + tid];
                su[tid] = s;
            }
            __syncthreads();
            layernorm_fused(su, ht, dln + ((l * 3 + 1) * 2) * DIM, tid, red2);

            // ---- FFN1 ----
            {
                int cc = tid & 127;
                const float* W1 = dw1 + l * DIM * FFD;
                const float4* Wp = (const float4*)(W1 + (q4 * 32) * FFD) + cc;
                const float* xp = ht + q4 * 32;
                float a[4] = {};
#pragma unroll
                for (int k = 0; k < 32; k++) {
                    float xk = xp[k];
                    float4 w = Wp[k * 128];
                    a[0] += xk * w.x; a[1] += xk * w.y;
                    a[2] += xk * w.z; a[3] += xk * w.w;
                }
                *(float4*)&pb0[q4 * 512 + cc * 4] = make_float4(a[0], a[1], a[2], a[3]);
            }
            __syncthreads();
            sf[tid] = fmaxf(db1[l * FFD + tid] + pb0[tid] + pb0[512 + tid]
                            + pb0[1024 + tid] + pb0[1536 + tid], 0.f);
            __syncthreads();
            // ---- FFN2 ----
            {
                const float* W2 = dw2 + l * FFD * DIM;
                const float4* Wp = (const float4*)(W2 + (q16 * 32) * DIM) + c;
                const float* xp = sf + q16 * 32;
                float a[4] = {};
#pragma unroll
                for (int k = 0; k < 32; k++) {
                    float xk = xp[k];
                    float4 w = Wp[k * 32];
                    a[0] += xk * w.x; a[1] += xk * w.y;
                    a[2] += xk * w.z; a[3] += xk * w.w;
                }
                *(float4*)&pb0[q16 * 128 + c * 4] = make_float4(a[0], a[1], a[2], a[3]);
            }
            __syncthreads();
            if (tid < 128) {
                float s = ht[tid] + db2[l * DIM + tid];
#pragma unroll
                for (int qq = 0; qq < 16; qq++) s += pb0[qq * 128 + tid];
                su[tid] = s;
            }
            __syncthreads();
            layernorm_fused(su, ht, dln + ((l * 3 + 2) * 2) * DIM, tid, red2);
        }

        // ---- final pointer logits ----
        {
            float a[4] = {};
            gemv4_part(ht, wqf, c, q16, a);
            *(float4*)&pb0[q16 * 128 + c * 4] = make_float4(a[0], a[1], a[2], a[3]);
        }
        __syncthreads();
        if (tid < 128) {
            float s = 0.f;
#pragma unroll
            for (int qq = 0; qq < 16; qq++) s += pb0[qq * 128 + tid];
            sq[tid] = s;
        }
        __syncthreads();
        if (tid < SEQ) {
            const float* kp = &sKfin[tid * KFPAD];
            float a0 = 0.f, a1 = 0.f, a2 = 0.f, a3 = 0.f;
#pragma unroll
            for (int k = 0; k < 128; k += 4) {
                a0 += sq[k] * kp[k];
                a1 += sq[k + 1] * kp[k + 1];
                a2 += sq[k + 2] * kp[k + 2];
                a3 += sq[k + 3] * kp[k + 3];
            }
            float s = (a0 + a1) + (a2 + a3);
            float lg = 10.f * tanhf(s * 0.08838834764831845f);
            slg[tid] = smask[tid] ? -1e9f : lg;
        }
        __syncthreads();
        if (tid < 32) {
            float v0 = (tid < SEQ) ? slg[tid] : -2e30f; int i0 = tid;
            float v1 = (tid + 32 < SEQ) ? slg[tid + 32] : -2e30f;
            if (v1 > v0) { v0 = v1; i0 = tid + 32; }
#pragma unroll
            for (int o = 16; o; o >>= 1) {
                float vo = __shfl_xor_sync(0xffffffffu, v0, o);
                int io = __shfl_xor_sync(0xffffffffu, i0, o);
                if (vo > v0 || (vo == v0 && io < i0)) { v0 = vo; i0 = io; }
            }
            float e0 = (tid < SEQ) ? expf(slg[tid] - v0) : 0.f;
            float e1 = (tid + 32 < SEQ) ? expf(slg[tid + 32] - v0) : 0.f;
            float sm = e0 + e1;
#pragma unroll
            for (int o = 16; o; o >>= 1) sm += __shfl_xor_sync(0xffffffffu, sm, o);
            if (tid == 0) {
                sslp += -logf(sm);
                smask[i0] = 1;
                scur = i0;
                out[b * NNOD + t] = (float)i0;
            }
        }
        __syncthreads();
    }
    if (tid == 0) out[BB * NNOD + b] = sslp;
}

// ---------------- host launcher ----------------
extern "C" void kernel_launch(void* const* d_in, const int* in_sizes, int n_in,
                              void* d_out, int out_size)
{
    const float* x          = (const float*)d_in[0];
    const float* w_input    = (const float*)d_in[1];
    const float* b_input    = (const float*)d_in[2];
    const float* start_ph   = (const float*)d_in[3];
    const float* enc_attn_w = (const float*)d_in[4];
    const float* enc_attn_b = (const float*)d_in[5];
    const float* enc_ffn_w1 = (const float*)d_in[6];
    const float* enc_ffn_b1 = (const float*)d_in[7];
    const float* enc_ffn_w2 = (const float*)d_in[8];
    const float* enc_ffn_b2 = (const float*)d_in[9];
    const float* enc_bn     = (const float*)d_in[10];
    const float* dec_self_w = (const float*)d_in[11];
    const float* dec_self_b = (const float*)d_in[12];
    const float* dec_cross_w= (const float*)d_in[13];
    const float* dec_cross_b= (const float*)d_in[14];
    const float* dec_ffn_w1 = (const float*)d_in[15];
    const float* dec_ffn_b1 = (const float*)d_in[16];
    const float* dec_ffn_w2 = (const float*)d_in[17];
    const float* dec_ffn_b2 = (const float*)d_in[18];
    const float* dec_ln     = (const float*)d_in[19];
    const float* wk_dec     = (const float*)d_in[20];
    const float* bk_dec     = (const float*)d_in[21];
    const float* wv_dec     = (const float*)d_in[22];
    const float* bv_dec     = (const float*)d_in[23];
    const float* wq_final   = (const float*)d_in[24];
    const float* wk_final   = (const float*)d_in[25];
    float* out = (float*)d_out;

    float* base = nullptr;
    cudaGetSymbolAddress((void**)&base, g_scratch);
    float* ph    = base + OFF_H0;
    float* pt1   = base + OFF_PT1;
    float* pt2   = base + OFF_PT2;
    float* pQ    = base + OFF_Q;
    float* pO    = base + OFF_O;
    float* pf    = base + OFF_F;
    float* pKatt = base + OFF_KATT;
    float* pVatt = base + OFF_VATT;
    float* pKfin = base + OFF_KFIN;
    float* ppart = base + OFF_PART;
    float* pbnA  = base + OFF_BNA;
    float* pbnB  = base + OFF_BNB;
    float* ppe   = base + OFF_PE;

    cudaFuncSetAttribute(decoder_kernel, cudaFuncAttributeMaxDynamicSharedMemorySize, DYN_BYTES);

    embed_kernel<<<(MTOT * DIM + 255) / 256, 256>>>(x, w_input, b_input, start_ph, ph);
    pe_kernel<<<(NNOD * DIM + 255) / 256, 256>>>(ppe);

    dim3 gDD(DIM / 64, MTOT / 64);
    dim3 gQKV(DIM / 64, MTOT / 64, 3);
    dim3 gDF(FFD / 64, MTOT / 64);
    dim3 gD2(256 / 64, MTOT / 64);

    for (int l = 0; l < NLE; l++) {
        const float* aw = enc_attn_w + (size_t)l * 4 * DIM * DIM;
        const float* ab = enc_attn_b + (size_t)l * 4 * DIM;
        const float* Araw = (l == 0) ? ph : pt2;

        if (l == 0)
            sgemm<true, false, false, true, false, false><<<gQKV, 256>>>(
                Araw, aw, ab, nullptr, pQ, nullptr, nullptr, MTOT, DIM, DIM);
        else
            sgemm<true, false, false, true, true, false><<<gQKV, 256>>>(
                Araw, aw, ab, nullptr, pQ, pbnB, nullptr, MTOT, DIM, DIM);

        enc_attn<<<BB * NH, 256>>>(pQ, pQ + SZ_MD, pQ + 2 * SZ_MD, pO);

        if (l == 0)
            sgemm<true, false, true, false, false, false><<<gDD, 256>>>(
                pO, aw + 3 * DIM * DIM, ab + 3 * DIM, Araw, pt1, nullptr, nullptr, MTOT, DIM, DIM);
        else
            sgemm<true, false, true, false, false, true><<<gDD, 256>>>(
                pO, aw + 3 * DIM * DIM, ab + 3 * DIM, Araw, pt1, nullptr, pbnB, MTOT, DIM, DIM);

        bn_stats<<<64, 256>>>(pt1, ppart, enc_bn + ((l * 2 + 0) * 2 + 0) * DIM,
                              enc_bn + ((l * 2 + 0) * 2 + 1) * DIM, pbnA);

        sgemm<true, true, false, false, true, false><<<gDF, 256>>>(
            pt1, enc_ffn_w1 + (size_t)l * DIM * FFD, enc_ffn_b1 + (size_t)l * FFD,
            nullptr, pf, pbnA, nullptr, MTOT, FFD, DIM);

        sgemm<true, false, true, false, false, true><<<gDD, 256>>>(
            pf, enc_ffn_w2 + (size_t)l * FFD * DIM, enc_ffn_b2 + (size_t)l * DIM,
            pt1, pt2, nullptr, pbnA, MTOT, DIM, FFD);

        bn_stats<<<64, 256>>>(pt2, ppart, enc_bn + ((l * 2 + 1) * 2 + 0) * DIM,
                              enc_bn + ((l * 2 + 1) * 2 + 1) * DIM, pbnB);
    }

    sgemm<true, false, false, false, true, false><<<gD2, 256>>>(
        pt2, wk_dec, bk_dec, nullptr, pKatt, pbnB, nullptr, MTOT, NLD * DIM, DIM);
    sgemm<true, false, false, false, true, false><<<gD2, 256>>>(
        pt2, wv_dec, bv_dec, nullptr, pVatt, pbnB, nullptr, MTOT, NLD * DIM, DIM);
    sgemm<false, false, false, false, true, false><<<gDD, 256>>>(
        pt2, wk_final, nullptr, nullptr, pKfin, pbnB, nullptr, MTOT, DIM, DIM);

    decoder_kernel<<<BB, 512, DYN_BYTES>>>(pt2, pbnB, ppe, pKatt, pVatt, pKfin,
                                dec_self_w, dec_self_b, dec_cross_w, dec_cross_b,
                                dec_ffn_w1, dec_ffn_b1, dec_ffn_w2, dec_ffn_b2,
                                dec_ln, wq_final, out);
}